// round 5
// baseline (speedup 1.0000x reference)
#include <cuda_runtime.h>
#include <cuda_fp16.h>
#include <cstdint>

#define B_DIM 4
#define T_DIM 4096
#define E_DIM 2048
#define H_DIM 16
#define D_DIM 128
#define BT_DIM 16384
#define KVSPLIT 8

typedef __half f16;

// ---------------- scratch (device globals; no allocations allowed) ----------
// int8 blocked planes: layout [row_block][k_tile(32)][g(16)][row(128)] 32-bit words,
// word (g,r) of a tile = int8 elements k = 4g..4g+3 of row r.
__device__ int8_t  g_xq1[(size_t)BT_DIM * E_DIM];
__device__ int8_t  g_xq2[(size_t)BT_DIM * E_DIM];
__device__ int8_t  g_Wq1[4][(size_t)E_DIM * E_DIM];
__device__ int8_t  g_Wq2[4][(size_t)E_DIM * E_DIM];
__device__ int8_t  g_ATq1[(size_t)BT_DIM * E_DIM];
__device__ int8_t  g_ATq2[(size_t)BT_DIM * E_DIM];
__device__ f16   g_Qh[(size_t)BT_DIM * E_DIM];
__device__ f16   g_Qc[(size_t)BT_DIM * E_DIM];
__device__ float g_K[(size_t)BT_DIM * E_DIM];
__device__ float g_V[(size_t)BT_DIM * E_DIM];
__device__ float g_ATT[(size_t)BT_DIM * E_DIM];
__device__ float g_KVp[(size_t)KVSPLIT * 64 * D_DIM * D_DIM];
__device__ f16   g_KVth[64 * D_DIM * D_DIM];
__device__ f16   g_KVtc[64 * D_DIM * D_DIM];
__device__ uint32_t g_absmax[8];   // 0=x, 1..4=Wq..Wo, 5=ATT

#define RATIO      254.0f
#define INV_RATIO  (1.0f / 254.0f)

// f16 compensated-pair constants (attn path)
#define SPLIT_S    32.0f
#define COMB_A     0.96875f
#define COMB_B     0.03125f

// ---------------- helpers ----------------------------------------------------
__device__ __forceinline__ uint32_t smem_u32(const void* p) {
    uint32_t a;
    asm("{ .reg .u64 t; cvta.to.shared.u64 t, %1; cvt.u32.u64 %0, t; }" : "=r"(a) : "l"(p));
    return a;
}
__device__ __forceinline__ void cp_async16(uint32_t sdst, const void* gsrc) {
    asm volatile("cp.async.cg.shared.global [%0], [%1], 16;" :: "r"(sdst), "l"(gsrc) : "memory");
}
#define CP_COMMIT() asm volatile("cp.async.commit_group;" ::: "memory")
#define CP_WAIT2()  asm volatile("cp.async.wait_group 2;" ::: "memory")

__device__ __forceinline__ uint32_t lds32(uint32_t a) {
    uint32_t v;
    asm volatile("ld.shared.b32 %0, [%1];" : "=r"(v) : "r"(a));
    return v;
}
__device__ __forceinline__ void ldsm4(uint32_t* r, uint32_t a) {
    asm volatile("ldmatrix.sync.aligned.m8n8.x4.shared.b16 {%0,%1,%2,%3}, [%4];"
                 : "=r"(r[0]), "=r"(r[1]), "=r"(r[2]), "=r"(r[3]) : "r"(a));
}
__device__ __forceinline__ void mma_f16(float* c, const uint32_t* a, const uint32_t* b) {
    asm volatile(
        "mma.sync.aligned.m16n8k16.row.col.f32.f16.f16.f32 "
        "{%0,%1,%2,%3}, {%4,%5,%6,%7}, {%8,%9}, {%0,%1,%2,%3};"
        : "+f"(c[0]), "+f"(c[1]), "+f"(c[2]), "+f"(c[3])
        : "r"(a[0]), "r"(a[1]), "r"(a[2]), "r"(a[3]), "r"(b[0]), "r"(b[1]));
}
__device__ __forceinline__ void mma_s8(int* c, const uint32_t* a, const uint32_t* b) {
    asm volatile(
        "mma.sync.aligned.m16n8k32.row.col.s32.s8.s8.s32 "
        "{%0,%1,%2,%3}, {%4,%5,%6,%7}, {%8,%9}, {%0,%1,%2,%3};"
        : "+r"(c[0]), "+r"(c[1]), "+r"(c[2]), "+r"(c[3])
        : "r"(a[0]), "r"(a[1]), "r"(a[2]), "r"(a[3]), "r"(b[0]), "r"(b[1]));
}
__device__ __forceinline__ void split2(float v, f16& h, f16& c) {
    h = __float2half_rn(v);
    float lo = v - __half2float(h);
    c = __float2half_rn(__half2float(h) + SPLIT_S * lo);
}

// ---------------- scale prep -------------------------------------------------
__global__ void k_zero_absmax() {
    if (threadIdx.x < 8) g_absmax[threadIdx.x] = 0u;
}

__global__ __launch_bounds__(256) void k_absmax(const float* __restrict__ in, size_t n4, int sidx)
{
    size_t i = blockIdx.x * 256 + threadIdx.x;
    size_t stride = (size_t)gridDim.x * 256;
    float m = 0.0f;
    for (; i < n4; i += stride) {
        float4 v = *reinterpret_cast<const float4*>(in + i * 4);
        m = fmaxf(m, fmaxf(fmaxf(fabsf(v.x), fabsf(v.y)), fmaxf(fabsf(v.z), fabsf(v.w))));
    }
    #pragma unroll
    for (int o = 16; o > 0; o >>= 1) m = fmaxf(m, __shfl_xor_sync(0xFFFFFFFFu, m, o));
    if ((threadIdx.x & 31) == 0) atomicMax(&g_absmax[sidx], __float_as_uint(m));
}

// fp32 row-major [R][2048] -> two blocked int8 planes. grid (32, R/128), block 256.
__global__ __launch_bounds__(256) void k_quant(const float* __restrict__ in, int sidx,
                                               int8_t* __restrict__ p1, int8_t* __restrict__ p2)
{
    const int kt = blockIdx.x;
    const int rb = blockIdx.y;
    const float am = __uint_as_float(g_absmax[sidx]);
    const float s1 = am * (1.0f / 127.0f);
    const float inv_s1 = 127.0f / am;
    uint32_t* o1 = reinterpret_cast<uint32_t*>(p1) + ((size_t)(rb * 32 + kt)) * 2048;
    uint32_t* o2 = reinterpret_cast<uint32_t*>(p2) + ((size_t)(rb * 32 + kt)) * 2048;
    #pragma unroll
    for (int i = 0; i < 8; i++) {
        int widx = threadIdx.x + i * 256;       // 0..2047
        int g = widx >> 7, r = widx & 127;
        float4 v = *reinterpret_cast<const float4*>(in + (size_t)(rb * 128 + r) * E_DIM + kt * 64 + g * 4);
        float vv[4] = {v.x, v.y, v.z, v.w};
        uint32_t w1 = 0, w2 = 0;
        #pragma unroll
        for (int q = 0; q < 4; q++) {
            int q1 = __float2int_rn(vv[q] * inv_s1);
            float r1 = vv[q] - s1 * (float)q1;
            int q2 = __float2int_rn(r1 * RATIO * inv_s1);
            w1 |= ((uint32_t)(uint8_t)(int8_t)q1) << (q * 8);
            w2 |= ((uint32_t)(uint8_t)(int8_t)q2) << (q * 8);
        }
        o1[widx] = w1;
        o2[widx] = w2;
    }
}

// ---------------- int8 GEMM --------------------------------------------------
// C[128,128] = sA*sB*[bankA + bankB/254] + bias, A/B two blocked int8 planes, K=2048.
// smem per plane tile: [g 16][136 words] (bank = 8g + r, conflict-free frags).
#define I8_PLANE  8704           // 16 * 136 * 4 bytes
#define I8_PA2    8704
#define I8_PB1    17408
#define I8_PB2    26112
#define I8_STAGE  34816
#define I8_SMEM   (3 * I8_STAGE)

__device__ __forceinline__ void load_plane_i8(uint32_t sdst, const int8_t* __restrict__ plane,
                                              int rb, int kt)
{
    const uint32_t* src = reinterpret_cast<const uint32_t*>(plane) + ((size_t)(rb * 32 + kt)) * 2048;
    const int t = threadIdx.x;
    #pragma unroll
    for (int i = 0; i < 2; i++) {
        int cid = t + i * 256;                 // 0..511
        int g = cid >> 5, r4 = (cid & 31) * 4;
        cp_async16(sdst + g * 544 + r4 * 4, src + g * 128 + r4);
    }
}

// OUT_MODE 0: fp32 (+bias).  OUT_MODE 1: f16 (h,c) pair (+bias).
template <int OUT_MODE>
__global__ __launch_bounds__(256, 1) void k_gemm_i8(
    const int8_t* __restrict__ A1, const int8_t* __restrict__ A2,
    const int8_t* __restrict__ B1, const int8_t* __restrict__ B2,
    int sa_idx, int sb_idx, const float* __restrict__ bias,
    float* __restrict__ Cf, f16* __restrict__ Chp, f16* __restrict__ Ccp)
{
    extern __shared__ __align__(1024) char smdyn[];
    const uint32_t sbase = smem_u32(smdyn);
    const int tid = threadIdx.x;
    const int wid = tid >> 5, lane = tid & 31;
    const int wm = (wid & 1) * 64;
    const int wn = (wid >> 1) * 32;
    const int rbA = blockIdx.y;
    const int rbB = blockIdx.x;
    const int gl = lane & 3;
    const int lr = lane >> 2;

    int accA[4][4][4];
    int accB[4][4][4];
    #pragma unroll
    for (int mi = 0; mi < 4; mi++)
        #pragma unroll
        for (int ni = 0; ni < 4; ni++)
            #pragma unroll
            for (int q = 0; q < 4; q++) { accA[mi][ni][q] = 0; accB[mi][ni][q] = 0; }

    #pragma unroll
    for (int i = 0; i < 2; i++) {
        uint32_t sb = sbase + i * I8_STAGE;
        load_plane_i8(sb + 0,      A1, rbA, i);
        load_plane_i8(sb + I8_PA2, A2, rbA, i);
        load_plane_i8(sb + I8_PB1, B1, rbB, i);
        load_plane_i8(sb + I8_PB2, B2, rbB, i);
        CP_COMMIT();
    }

    for (int c = 0; c < 32; c++) {
        if (c + 2 < 32) {
            uint32_t sb = sbase + ((c + 2) % 3) * I8_STAGE;
            load_plane_i8(sb + 0,      A1, rbA, c + 2);
            load_plane_i8(sb + I8_PA2, A2, rbA, c + 2);
            load_plane_i8(sb + I8_PB1, B1, rbB, c + 2);
            load_plane_i8(sb + I8_PB2, B2, rbB, c + 2);
        }
        CP_COMMIT();
        CP_WAIT2();
        __syncthreads();

        const uint32_t sb = sbase + (c % 3) * I8_STAGE;
        #pragma unroll
        for (int ks = 0; ks < 2; ks++) {
            const uint32_t gbase = (8 * ks + gl) * 544;
            uint32_t a1[4][4], a2[4][4], b1[4][2], b2[4][2];
            #pragma unroll
            for (int mi = 0; mi < 4; mi++) {
                uint32_t ra = (wm + mi * 16 + lr) * 4;
                uint32_t ad = sb + gbase + ra;
                a1[mi][0] = lds32(ad);          a1[mi][1] = lds32(ad + 32);
                a1[mi][2] = lds32(ad + 2176);   a1[mi][3] = lds32(ad + 2208);
                ad += I8_PA2;
                a2[mi][0] = lds32(ad);          a2[mi][1] = lds32(ad + 32);
                a2[mi][2] = lds32(ad + 2176);   a2[mi][3] = lds32(ad + 2208);
            }
            #pragma unroll
            for (int ni = 0; ni < 4; ni++) {
                uint32_t rbw = (wn + ni * 8 + lr) * 4;
                uint32_t bd = sb + I8_PB1 + gbase + rbw;
                b1[ni][0] = lds32(bd);          b1[ni][1] = lds32(bd + 2176);
                bd += (I8_PB2 - I8_PB1);
                b2[ni][0] = lds32(bd);          b2[ni][1] = lds32(bd + 2176);
            }
            #pragma unroll
            for (int mi = 0; mi < 4; mi++)
                #pragma unroll
                for (int ni = 0; ni < 4; ni++) {
                    mma_s8(accA[mi][ni], a1[mi], b1[ni]);
                    mma_s8(accB[mi][ni], a1[mi], b2[ni]);
                    mma_s8(accB[mi][ni], a2[mi], b1[ni]);
                }
        }
        __syncthreads();
    }

    const float s = (__uint_as_float(g_absmax[sa_idx]) * (1.0f / 127.0f)) *
                    (__uint_as_float(g_absmax[sb_idx]) * (1.0f / 127.0f));
    const int lg = lane >> 2;
    const int lc2 = (lane & 3) * 2;
    #pragma unroll
    for (int mi = 0; mi < 4; mi++) {
        #pragma unroll
        for (int half = 0; half < 2; half++) {
            int row = rbA * 128 + wm + mi * 16 + lg + half * 8;
            #pragma unroll
            for (int ni = 0; ni < 4; ni++) {
                int col = rbB * 128 + wn + ni * 8 + lc2;
                float v0 = s * ((float)accA[mi][ni][half * 2 + 0] + (float)accB[mi][ni][half * 2 + 0] * INV_RATIO);
                float v1 = s * ((float)accA[mi][ni][half * 2 + 1] + (float)accB[mi][ni][half * 2 + 1] * INV_RATIO);
                v0 += bias[col]; v1 += bias[col + 1];
                if (OUT_MODE == 0) {
                    *reinterpret_cast<float2*>(Cf + (size_t)row * E_DIM + col) = make_float2(v0, v1);
                } else {
                    f16 h0, c0, h1, c1;
                    split2(v0, h0, c0);
                    split2(v1, h1, c1);
                    uint32_t hw = (uint32_t)__half_as_ushort(h0) | ((uint32_t)__half_as_ushort(h1) << 16);
                    uint32_t cw = (uint32_t)__half_as_ushort(c0) | ((uint32_t)__half_as_ushort(c1) << 16);
                    *reinterpret_cast<uint32_t*>(Chp + (size_t)row * E_DIM + col) = hw;
                    *reinterpret_cast<uint32_t*>(Ccp + (size_t)row * E_DIM + col) = cw;
                }
            }
        }
    }
}

// ---------------- f16 compensated attn GEMM (Q @ KVt per head) ---------------
#define F16_STAGE 32768
#define F16_SMEM  (3 * F16_STAGE)

__device__ __forceinline__ void load_tile_f16(uint32_t sdst, const f16* __restrict__ g,
                                              int row0, int col0, int ld) {
    const int t = threadIdx.x;
    #pragma unroll
    for (int i = 0; i < 2; i++) {
        int idx = t + i * 256;
        int r = idx >> 2, c = idx & 3;
        const f16* src = g + (size_t)(row0 + r) * ld + col0 + c * 8;
        uint32_t off = r * 64 + ((c ^ ((r >> 1) & 3)) << 4);
        cp_async16(sdst + off, src);
    }
}

__global__ __launch_bounds__(256) void k_gemm_attn()
{
    const float alpha = 0.08838834764831845f;   // 1/sqrt(128)
    const int h = blockIdx.z;
    const int row0 = blockIdx.y * 128;
    const int b = row0 >> 12;
    const int bh = (b << 4) + h;
    const f16* Ah = g_Qh;
    const f16* Ac = g_Qc;
    const f16* Bh = g_KVth + ((size_t)bh << 14);
    const f16* Bc = g_KVtc + ((size_t)bh << 14);
    const int acol = h * 128;

    extern __shared__ __align__(1024) char smdyn[];
    const uint32_t sbase = smem_u32(smdyn);
    const int tid = threadIdx.x;
    const int wid = tid >> 5, lane = tid & 31;
    const int wm = (wid & 1) * 64;
    const int wn = (wid >> 1) * 32;

    uint32_t aoff[4][2];
    #pragma unroll
    for (int mi = 0; mi < 4; mi++) {
        int r = wm + mi * 16 + (lane & 15);
        #pragma unroll
        for (int ks = 0; ks < 2; ks++) {
            int kc = ks * 2 + (lane >> 4);
            aoff[mi][ks] = r * 64 + ((kc ^ ((r >> 1) & 3)) << 4);
        }
    }
    uint32_t boff[2][2];
    #pragma unroll
    for (int p = 0; p < 2; p++) {
        int g2 = lane >> 3;
        int r = wn + p * 16 + ((g2 >> 1) << 3) + (lane & 7);
        #pragma unroll
        for (int ks = 0; ks < 2; ks++) {
            int kc = ks * 2 + (g2 & 1);
            boff[p][ks] = r * 64 + ((kc ^ ((r >> 1) & 3)) << 4);
        }
    }

    float accA[4][4][4], accB[4][4][4];
    #pragma unroll
    for (int mi = 0; mi < 4; mi++)
        #pragma unroll
        for (int ni = 0; ni < 4; ni++)
            #pragma unroll
            for (int q = 0; q < 4; q++) { accA[mi][ni][q] = 0.0f; accB[mi][ni][q] = 0.0f; }

    #pragma unroll
    for (int i = 0; i < 2; i++) {
        uint32_t sb = sbase + i * F16_STAGE;
        int k0 = i * 32;
        load_tile_f16(sb + 0,     Ah, row0, acol + k0, E_DIM);
        load_tile_f16(sb + 8192,  Ac, row0, acol + k0, E_DIM);
        load_tile_f16(sb + 16384, Bh, 0, k0, D_DIM);
        load_tile_f16(sb + 24576, Bc, 0, k0, D_DIM);
        CP_COMMIT();
    }

    for (int c = 0; c < 4; c++) {
        if (c + 2 < 4) {
            uint32_t sb = sbase + ((c + 2) % 3) * F16_STAGE;
            int k0 = (c + 2) * 32;
            load_tile_f16(sb + 0,     Ah, row0, acol + k0, E_DIM);
            load_tile_f16(sb + 8192,  Ac, row0, acol + k0, E_DIM);
            load_tile_f16(sb + 16384, Bh, 0, k0, D_DIM);
            load_tile_f16(sb + 24576, Bc, 0, k0, D_DIM);
        }
        CP_COMMIT();
        CP_WAIT2();
        __syncthreads();

        const uint32_t sb = sbase + (c % 3) * F16_STAGE;
        #pragma unroll
        for (int ks = 0; ks < 2; ks++) {
            uint32_t ah[4][4], a2[4][4], bh[4][2], b2[4][2];
            #pragma unroll
            for (int mi = 0; mi < 4; mi++) {
                ldsm4(ah[mi], sb + aoff[mi][ks]);
                ldsm4(a2[mi], sb + 8192 + aoff[mi][ks]);
            }
            #pragma unroll
            for (int p = 0; p < 2; p++) {
                uint32_t t4[4];
                ldsm4(t4, sb + 16384 + boff[p][ks]);
                bh[2 * p][0] = t4[0]; bh[2 * p][1] = t4[1];
                bh[2 * p + 1][0] = t4[2]; bh[2 * p + 1][1] = t4[3];
                ldsm4(t4, sb + 24576 + boff[p][ks]);
                b2[2 * p][0] = t4[0]; b2[2 * p][1] = t4[1];
                b2[2 * p + 1][0] = t4[2]; b2[2 * p + 1][1] = t4[3];
            }
            #pragma unroll
            for (int mi = 0; mi < 4; mi++)
                #pragma unroll
                for (int ni = 0; ni < 4; ni++) {
                    mma_f16(accA[mi][ni], ah[mi], bh[ni]);
                    mma_f16(accB[mi][ni], a2[mi], b2[ni]);
                }
        }
        __syncthreads();
    }

    // epilogue: fp32 ATT + absmax
    float lmax = 0.0f;
    const int lg = lane >> 2;
    const int lc2 = (lane & 3) * 2;
    #pragma unroll
    for (int mi = 0; mi < 4; mi++) {
        #pragma unroll
        for (int half = 0; half < 2; half++) {
            int row = row0 + wm + mi * 16 + lg + half * 8;
            #pragma unroll
            for (int ni = 0; ni < 4; ni++) {
                int col = h * 128 + wn + ni * 8 + lc2;
                float v0 = alpha * (COMB_A * accA[mi][ni][half * 2 + 0] + COMB_B * accB[mi][ni][half * 2 + 0]);
                float v1 = alpha * (COMB_A * accA[mi][ni][half * 2 + 1] + COMB_B * accB[mi][ni][half * 2 + 1]);
                lmax = fmaxf(lmax, fmaxf(fabsf(v0), fabsf(v1)));
                *reinterpret_cast<float2*>(g_ATT + (size_t)row * E_DIM + col) = make_float2(v0, v1);
            }
        }
    }
    #pragma unroll
    for (int o = 16; o > 0; o >>= 1) lmax = fmaxf(lmax, __shfl_xor_sync(0xFFFFFFFFu, lmax, o));
    if (lane == 0) atomicMax(&g_absmax[5], __float_as_uint(lmax));
}

// ---------------- KV^T (split-K SIMT fp32) -----------------------------------
__global__ __launch_bounds__(256, 2) void k_kvpart()
{
    const int split = blockIdx.x;
    const int bh = blockIdx.z;
    const int b = bh >> 4;
    const int h = bh & 15;
    const float* A  = g_V + (size_t)b * T_DIM * E_DIM + h * D_DIM;
    const float* Bk = g_K + (size_t)b * T_DIM * E_DIM + h * D_DIM;
    float* Cg = g_KVp + ((size_t)(split * 64 + bh) << 14);

    __shared__ float As[16][D_DIM];
    __shared__ float Bs[16][D_DIM];

    const int tid = threadIdx.x;
    const int lr = tid >> 5;
    const int lc = (tid & 31) << 2;
    const int ty = tid >> 4;
    const int tx = tid & 15;

    float acc[8][8];
    #pragma unroll
    for (int i = 0; i < 8; i++)
        #pragma unroll
        for (int j = 0; j < 8; j++) acc[i][j] = 0.0f;

    const int s_begin = split * (T_DIM / KVSPLIT);
    const int s_end = s_begin + (T_DIM / KVSPLIT);
    for (int s0 = s_begin; s0 < s_end; s0 += 16) {
        #pragma unroll
        for (int rr = 0; rr < 2; rr++) {
            int sdx = lr + rr * 8;
            *reinterpret_cast<float4*>(&As[sdx][lc]) =
                *reinterpret_cast<const float4*>(A + (size_t)(s0 + sdx) * E_DIM + lc);
            *reinterpret_cast<float4*>(&Bs[sdx][lc]) =
                *reinterpret_cast<const float4*>(Bk + (size_t)(s0 + sdx) * E_DIM + lc);
        }
        __syncthreads();
        #pragma unroll
        for (int k = 0; k < 16; k++) {
            float a[8], bb[8];
            *reinterpret_cast<float4*>(a)      = *reinterpret_cast<const float4*>(&As[k][ty * 8]);
            *reinterpret_cast<float4*>(a + 4)  = *reinterpret_cast<const float4*>(&As[k][ty * 8 + 4]);
            *reinterpret_cast<float4*>(bb)     = *reinterpret_cast<const float4*>(&Bs[k][tx * 8]);
            *reinterpret_cast<float4*>(bb + 4) = *reinterpret_cast<const float4*>(&Bs[k][tx * 8 + 4]);
            #pragma unroll
            for (int i = 0; i < 8; i++)
                #pragma unroll
                for (int j = 0; j < 8; j++) acc[i][j] += a[i] * bb[j];
        }
        __syncthreads();
    }

    #pragma unroll
    for (int i = 0; i < 8; i++) {
        float* Cr = Cg + (ty * 8 + i) * D_DIM + tx * 8;
        #pragma unroll
        for (int j = 0; j < 8; j += 4)
            *reinterpret_cast<float4*>(Cr + j) = make_float4(acc[i][j], acc[i][j + 1], acc[i][j + 2], acc[i][j + 3]);
    }
}

__global__ __launch_bounds__(256) void k_kvreduce()
{
    int idx = blockIdx.x * 256 + threadIdx.x;
    float sv = 0.0f;
    #pragma unroll
    for (int p = 0; p < KVSPLIT; p++) sv += g_KVp[((size_t)p << 20) + idx];
    f16 h, c;
    split2(sv, h, c);
    g_KVth[idx] = h;
    g_KVtc[idx] = c;
}

// ---------------- launch -----------------------------------------------------
extern "C" void kernel_launch(void* const* d_in, const int* in_sizes, int n_in,
                              void* d_out, int out_size)
{
    const float* x  = (const float*)d_in[0];
    const float* Wq = (const float*)d_in[1];
    const float* bq = (const float*)d_in[2];
    const float* Wk = (const float*)d_in[3];
    const float* bk = (const float*)d_in[4];
    const float* Wv = (const float*)d_in[5];
    const float* bv = (const float*)d_in[6];
    const float* Wo = (const float*)d_in[7];
    const float* bo = (const float*)d_in[8];
    float* out = (float*)d_out;

    int8_t *xq1, *xq2, *wq1, *wq2, *atq1, *atq2;
    f16 *qh, *qc;
    float *Kf, *Vf, *ATT;
    cudaGetSymbolAddress((void**)&xq1, g_xq1);
    cudaGetSymbolAddress((void**)&xq2, g_xq2);
    cudaGetSymbolAddress((void**)&wq1, g_Wq1);
    cudaGetSymbolAddress((void**)&wq2, g_Wq2);
    cudaGetSymbolAddress((void**)&atq1, g_ATq1);
    cudaGetSymbolAddress((void**)&atq2, g_ATq2);
    cudaGetSymbolAddress((void**)&qh, g_Qh);
    cudaGetSymbolAddress((void**)&qc, g_Qc);
    cudaGetSymbolAddress((void**)&Kf, g_K);
    cudaGetSymbolAddress((void**)&Vf, g_V);
    cudaGetSymbolAddress((void**)&ATT, g_ATT);

    cudaFuncSetAttribute(k_gemm_i8<0>, cudaFuncAttributeMaxDynamicSharedMemorySize, I8_SMEM);
    cudaFuncSetAttribute(k_gemm_i8<1>, cudaFuncAttributeMaxDynamicSharedMemorySize, I8_SMEM);
    cudaFuncSetAttribute(k_gemm_attn,  cudaFuncAttributeMaxDynamicSharedMemorySize, F16_SMEM);

    const size_t WSZ = (size_t)E_DIM * E_DIM;
    const size_t NX = (size_t)BT_DIM * E_DIM;

    k_zero_absmax<<<1, 32>>>();
    k_absmax<<<512, 256>>>(x, NX / 4, 0);
    k_absmax<<<128, 256>>>(Wq, WSZ / 4, 1);
    k_absmax<<<128, 256>>>(Wk, WSZ / 4, 2);
    k_absmax<<<128, 256>>>(Wv, WSZ / 4, 3);
    k_absmax<<<128, 256>>>(Wo, WSZ / 4, 4);

    k_quant<<<dim3(32, 128), 256>>>(x, 0, xq1, xq2);
    k_quant<<<dim3(32, 16), 256>>>(Wq, 1, wq1 + 0 * WSZ, wq2 + 0 * WSZ);
    k_quant<<<dim3(32, 16), 256>>>(Wk, 2, wq1 + 1 * WSZ, wq2 + 1 * WSZ);
    k_quant<<<dim3(32, 16), 256>>>(Wv, 3, wq1 + 2 * WSZ, wq2 + 2 * WSZ);
    k_quant<<<dim3(32, 16), 256>>>(Wo, 4, wq1 + 3 * WSZ, wq2 + 3 * WSZ);

    dim3 gp(E_DIM / 128, BT_DIM / 128);   // (16, 128)
    k_gemm_i8<1><<<gp, 256, I8_SMEM>>>(xq1, xq2, wq1 + 0 * WSZ, wq2 + 0 * WSZ, 0, 1, bq, nullptr, qh, qc);
    k_gemm_i8<0><<<gp, 256, I8_SMEM>>>(xq1, xq2, wq1 + 1 * WSZ, wq2 + 1 * WSZ, 0, 2, bk, Kf, nullptr, nullptr);
    k_gemm_i8<0><<<gp, 256, I8_SMEM>>>(xq1, xq2, wq1 + 2 * WSZ, wq2 + 2 * WSZ, 0, 3, bv, Vf, nullptr, nullptr);

    k_kvpart<<<dim3(KVSPLIT, 1, 64), 256>>>();
    k_kvreduce<<<(64 * D_DIM * D_DIM) / 256, 256>>>();

    k_gemm_attn<<<dim3(1, BT_DIM / 128, H_DIM), 256, F16_SMEM>>>();

    k_quant<<<dim3(32, 128), 256>>>(ATT, 5, atq1, atq2);

    k_gemm_i8<0><<<gp, 256, I8_SMEM>>>(atq1, atq2, wq1 + 3 * WSZ, wq2 + 3 * WSZ, 5, 4, bo, out, nullptr, nullptr);
}

// round 6
// speedup vs baseline: 3.5856x; 3.5856x over previous
#include <cuda_runtime.h>
#include <cuda_fp16.h>
#include <cstdint>

#define B_DIM 4
#define T_DIM 4096
#define E_DIM 2048
#define H_DIM 16
#define D_DIM 128
#define BT_DIM 16384
#define KVSPLIT 8

typedef __half f16;

// ---------------- scratch (device globals; no allocations allowed) ----------
// pair convention: h = fp16(v); c = fp16((h + 32*(v-h)) / sqrt(31))
// GEMM: acc = sum h_a h_b + sum c_a c_b ; result = (31/32) * acc
__device__ f16 g_xh[(size_t)BT_DIM * E_DIM];
__device__ f16 g_xc[(size_t)BT_DIM * E_DIM];
__device__ f16 g_Wh[4][(size_t)E_DIM * E_DIM];
__device__ f16 g_Wc[4][(size_t)E_DIM * E_DIM];
__device__ f16 g_Qh[(size_t)BT_DIM * E_DIM];
__device__ f16 g_Qc[(size_t)BT_DIM * E_DIM];
__device__ float g_K[(size_t)BT_DIM * E_DIM];
__device__ float g_V[(size_t)BT_DIM * E_DIM];
__device__ f16 g_ATh[(size_t)BT_DIM * E_DIM];
__device__ f16 g_ATc[(size_t)BT_DIM * E_DIM];
__device__ float g_KVp[(size_t)KVSPLIT * 64 * D_DIM * D_DIM];
__device__ f16 g_KVth[64 * D_DIM * D_DIM];
__device__ f16 g_KVtc[64 * D_DIM * D_DIM];

#define SPLIT_S     32.0f
#define INV_SQRT31  0.17960530202677491f
#define COMB_SCALE  0.96875f          // 31/32

// ---------------- helpers ----------------------------------------------------
__device__ __forceinline__ uint32_t smem_u32(const void* p) {
    uint32_t a;
    asm("{ .reg .u64 t; cvta.to.shared.u64 t, %1; cvt.u32.u64 %0, t; }" : "=r"(a) : "l"(p));
    return a;
}
__device__ __forceinline__ void cp_async16(uint32_t sdst, const void* gsrc) {
    asm volatile("cp.async.cg.shared.global [%0], [%1], 16;" :: "r"(sdst), "l"(gsrc) : "memory");
}
#define CP_COMMIT() asm volatile("cp.async.commit_group;" ::: "memory")
#define CP_WAIT2()  asm volatile("cp.async.wait_group 2;" ::: "memory")

__device__ __forceinline__ void ldsm4(uint32_t* r, uint32_t a) {
    asm volatile("ldmatrix.sync.aligned.m8n8.x4.shared.b16 {%0,%1,%2,%3}, [%4];"
                 : "=r"(r[0]), "=r"(r[1]), "=r"(r[2]), "=r"(r[3]) : "r"(a));
}
__device__ __forceinline__ void mma_f16(float* c, const uint32_t* a, const uint32_t* b) {
    asm volatile(
        "mma.sync.aligned.m16n8k16.row.col.f32.f16.f16.f32 "
        "{%0,%1,%2,%3}, {%4,%5,%6,%7}, {%8,%9}, {%0,%1,%2,%3};"
        : "+f"(c[0]), "+f"(c[1]), "+f"(c[2]), "+f"(c[3])
        : "r"(a[0]), "r"(a[1]), "r"(a[2]), "r"(a[3]), "r"(b[0]), "r"(b[1]));
}
__device__ __forceinline__ void split2(float v, f16& h, f16& c) {
    h = __float2half_rn(v);
    float lo = v - __half2float(h);
    c = __float2half_rn((__half2float(h) + SPLIT_S * lo) * INV_SQRT31);
}

// ---------------- big GEMM: CTA 128x256, warp 64x64, 8 warps -----------------
// A[M,K] row-major pairs (Ah,Ac); B[N,K] row-major pairs (Bh,Bc); C = (31/32)(AhBh^T + AcBc^T)
// smem tile row layout: 64B/row (32 f16), 16B chunk c swizzled by c ^ ((r>>1)&3).
#define PG_AH 0
#define PG_AC 8192
#define PG_BH 16384
#define PG_BC 32768
#define PG_STAGE 49152
#define PG_SMEM  (3 * PG_STAGE)

__device__ __forceinline__ void load_rows(uint32_t sdst, const f16* __restrict__ g,
                                          int row0, int col0, int ld, int nrows_log2) {
    // nrows_log2: 7 -> 128 rows (2 iters), 8 -> 256 rows (4 iters)
    const int t = threadIdx.x;
    const int iters = 1 << (nrows_log2 - 6);   // rows*4chunks/256threads
    #pragma unroll 4
    for (int i = 0; i < iters; i++) {
        int idx = t + i * 256;
        int r = idx >> 2, c = idx & 3;
        const f16* src = g + (size_t)(row0 + r) * ld + col0 + c * 8;
        uint32_t off = r * 64 + ((c ^ ((r >> 1) & 3)) << 4);
        cp_async16(sdst + off, src);
    }
}

// OUT_MODE 0: fp32 (+bias).  OUT_MODE 1: (h,c) pair (+bias).
template <int OUT_MODE>
__global__ __launch_bounds__(256, 1) void k_gemm_proj(
    const f16* __restrict__ Ah, const f16* __restrict__ Ac,
    const f16* __restrict__ Bh, const f16* __restrict__ Bc,
    const float* __restrict__ bias,
    float* __restrict__ Cf, f16* __restrict__ Chp, f16* __restrict__ Ccp)
{
    extern __shared__ __align__(1024) char smdyn[];
    const uint32_t sbase = smem_u32(smdyn);
    const int tid = threadIdx.x;
    const int wid = tid >> 5, lane = tid & 31;
    const int wm = (wid & 1) * 64;       // warp row offset in 128
    const int wn = (wid >> 1) * 64;      // warp col offset in 256
    const int row0 = blockIdx.y * 128;
    const int n0 = blockIdx.x * 256;

    uint32_t aoff[4][2];
    #pragma unroll
    for (int mi = 0; mi < 4; mi++) {
        int r = wm + mi * 16 + (lane & 15);
        #pragma unroll
        for (int ks = 0; ks < 2; ks++) {
            int kc = ks * 2 + (lane >> 4);
            aoff[mi][ks] = r * 64 + ((kc ^ ((r >> 1) & 3)) << 4);
        }
    }
    uint32_t boff[4][2];
    #pragma unroll
    for (int p = 0; p < 4; p++) {
        int g2 = lane >> 3;
        int r = wn + p * 16 + ((g2 >> 1) << 3) + (lane & 7);
        #pragma unroll
        for (int ks = 0; ks < 2; ks++) {
            int kc = ks * 2 + (g2 & 1);
            boff[p][ks] = r * 64 + ((kc ^ ((r >> 1) & 3)) << 4);
        }
    }

    float acc[4][8][4];
    #pragma unroll
    for (int mi = 0; mi < 4; mi++)
        #pragma unroll
        for (int ni = 0; ni < 8; ni++)
            #pragma unroll
            for (int q = 0; q < 4; q++) acc[mi][ni][q] = 0.0f;

    #pragma unroll
    for (int i = 0; i < 2; i++) {
        uint32_t sb = sbase + i * PG_STAGE;
        int k0 = i * 32;
        load_rows(sb + PG_AH, Ah, row0, k0, E_DIM, 7);
        load_rows(sb + PG_AC, Ac, row0, k0, E_DIM, 7);
        load_rows(sb + PG_BH, Bh, n0, k0, E_DIM, 8);
        load_rows(sb + PG_BC, Bc, n0, k0, E_DIM, 8);
        CP_COMMIT();
    }

    for (int c = 0; c < 64; c++) {
        if (c + 2 < 64) {
            uint32_t sb = sbase + ((c + 2) % 3) * PG_STAGE;
            int k0 = (c + 2) * 32;
            load_rows(sb + PG_AH, Ah, row0, k0, E_DIM, 7);
            load_rows(sb + PG_AC, Ac, row0, k0, E_DIM, 7);
            load_rows(sb + PG_BH, Bh, n0, k0, E_DIM, 8);
            load_rows(sb + PG_BC, Bc, n0, k0, E_DIM, 8);
        }
        CP_COMMIT();
        CP_WAIT2();
        __syncthreads();

        const uint32_t sb = sbase + (c % 3) * PG_STAGE;
        #pragma unroll
        for (int ks = 0; ks < 2; ks++) {
            uint32_t ah[4][4], a2[4][4], bh[8][2], b2[8][2];
            #pragma unroll
            for (int mi = 0; mi < 4; mi++) {
                ldsm4(ah[mi], sb + PG_AH + aoff[mi][ks]);
                ldsm4(a2[mi], sb + PG_AC + aoff[mi][ks]);
            }
            #pragma unroll
            for (int p = 0; p < 4; p++) {
                uint32_t t4[4];
                ldsm4(t4, sb + PG_BH + boff[p][ks]);
                bh[2 * p][0] = t4[0]; bh[2 * p][1] = t4[1];
                bh[2 * p + 1][0] = t4[2]; bh[2 * p + 1][1] = t4[3];
                ldsm4(t4, sb + PG_BC + boff[p][ks]);
                b2[2 * p][0] = t4[0]; b2[2 * p][1] = t4[1];
                b2[2 * p + 1][0] = t4[2]; b2[2 * p + 1][1] = t4[3];
            }
            #pragma unroll
            for (int mi = 0; mi < 4; mi++)
                #pragma unroll
                for (int ni = 0; ni < 8; ni++) {
                    mma_f16(acc[mi][ni], ah[mi], bh[ni]);
                    mma_f16(acc[mi][ni], a2[mi], b2[ni]);
                }
        }
        __syncthreads();
    }

    const int lg = lane >> 2;
    const int lc2 = (lane & 3) * 2;
    #pragma unroll
    for (int mi = 0; mi < 4; mi++) {
        #pragma unroll
        for (int half = 0; half < 2; half++) {
            int row = row0 + wm + mi * 16 + lg + half * 8;
            #pragma unroll
            for (int ni = 0; ni < 8; ni++) {
                int col = n0 + wn + ni * 8 + lc2;
                float v0 = COMB_SCALE * acc[mi][ni][half * 2 + 0] + bias[col];
                float v1 = COMB_SCALE * acc[mi][ni][half * 2 + 1] + bias[col + 1];
                if (OUT_MODE == 0) {
                    *reinterpret_cast<float2*>(Cf + (size_t)row * E_DIM + col) = make_float2(v0, v1);
                } else {
                    f16 h0, c0, h1, c1;
                    split2(v0, h0, c0);
                    split2(v1, h1, c1);
                    uint32_t hw = (uint32_t)__half_as_ushort(h0) | ((uint32_t)__half_as_ushort(h1) << 16);
                    uint32_t cw = (uint32_t)__half_as_ushort(c0) | ((uint32_t)__half_as_ushort(c1) << 16);
                    *reinterpret_cast<uint32_t*>(Chp + (size_t)row * E_DIM + col) = hw;
                    *reinterpret_cast<uint32_t*>(Ccp + (size_t)row * E_DIM + col) = cw;
                }
            }
        }
    }
}

// ---------------- attn GEMM: CTA 128x128, K=128, merged acc ------------------
#define AT_STAGE 32768
#define AT_SMEM  (3 * AT_STAGE)

__device__ __forceinline__ void load_tile128(uint32_t sdst, const f16* __restrict__ g,
                                             int row0, int col0, int ld) {
    const int t = threadIdx.x;
    #pragma unroll
    for (int i = 0; i < 2; i++) {
        int idx = t + i * 256;
        int r = idx >> 2, c = idx & 3;
        const f16* src = g + (size_t)(row0 + r) * ld + col0 + c * 8;
        uint32_t off = r * 64 + ((c ^ ((r >> 1) & 3)) << 4);
        cp_async16(sdst + off, src);
    }
}

__global__ __launch_bounds__(256) void k_gemm_attn()
{
    const float alpha = 0.08838834764831845f * COMB_SCALE;
    const int h = blockIdx.z;
    const int row0 = blockIdx.y * 128;
    const int b = row0 >> 12;
    const int bh = (b << 4) + h;
    const f16* Ah = g_Qh;
    const f16* Ac = g_Qc;
    const f16* Bh = g_KVth + ((size_t)bh << 14);
    const f16* Bc = g_KVtc + ((size_t)bh << 14);
    const int acol = h * 128;

    extern __shared__ __align__(1024) char smdyn[];
    const uint32_t sbase = smem_u32(smdyn);
    const int tid = threadIdx.x;
    const int wid = tid >> 5, lane = tid & 31;
    const int wm = (wid & 1) * 64;
    const int wn = (wid >> 1) * 32;

    uint32_t aoff[4][2];
    #pragma unroll
    for (int mi = 0; mi < 4; mi++) {
        int r = wm + mi * 16 + (lane & 15);
        #pragma unroll
        for (int ks = 0; ks < 2; ks++) {
            int kc = ks * 2 + (lane >> 4);
            aoff[mi][ks] = r * 64 + ((kc ^ ((r >> 1) & 3)) << 4);
        }
    }
    uint32_t boff[2][2];
    #pragma unroll
    for (int p = 0; p < 2; p++) {
        int g2 = lane >> 3;
        int r = wn + p * 16 + ((g2 >> 1) << 3) + (lane & 7);
        #pragma unroll
        for (int ks = 0; ks < 2; ks++) {
            int kc = ks * 2 + (g2 & 1);
            boff[p][ks] = r * 64 + ((kc ^ ((r >> 1) & 3)) << 4);
        }
    }

    float acc[4][4][4];
    #pragma unroll
    for (int mi = 0; mi < 4; mi++)
        #pragma unroll
        for (int ni = 0; ni < 4; ni++)
            #pragma unroll
            for (int q = 0; q < 4; q++) acc[mi][ni][q] = 0.0f;

    #pragma unroll
    for (int i = 0; i < 2; i++) {
        uint32_t sb = sbase + i * AT_STAGE;
        int k0 = i * 32;
        load_tile128(sb + 0,     Ah, row0, acol + k0, E_DIM);
        load_tile128(sb + 8192,  Ac, row0, acol + k0, E_DIM);
        load_tile128(sb + 16384, Bh, 0, k0, D_DIM);
        load_tile128(sb + 24576, Bc, 0, k0, D_DIM);
        CP_COMMIT();
    }

    for (int c = 0; c < 4; c++) {
        if (c + 2 < 4) {
            uint32_t sb = sbase + ((c + 2) % 3) * AT_STAGE;
            int k0 = (c + 2) * 32;
            load_tile128(sb + 0,     Ah, row0, acol + k0, E_DIM);
            load_tile128(sb + 8192,  Ac, row0, acol + k0, E_DIM);
            load_tile128(sb + 16384, Bh, 0, k0, D_DIM);
            load_tile128(sb + 24576, Bc, 0, k0, D_DIM);
        }
        CP_COMMIT();
        CP_WAIT2();
        __syncthreads();

        const uint32_t sb = sbase + (c % 3) * AT_STAGE;
        #pragma unroll
        for (int ks = 0; ks < 2; ks++) {
            uint32_t ah[4][4], a2[4][4], bh[4][2], b2[4][2];
            #pragma unroll
            for (int mi = 0; mi < 4; mi++) {
                ldsm4(ah[mi], sb + aoff[mi][ks]);
                ldsm4(a2[mi], sb + 8192 + aoff[mi][ks]);
            }
            #pragma unroll
            for (int p = 0; p < 2; p++) {
                uint32_t t4[4];
                ldsm4(t4, sb + 16384 + boff[p][ks]);
                bh[2 * p][0] = t4[0]; bh[2 * p][1] = t4[1];
                bh[2 * p + 1][0] = t4[2]; bh[2 * p + 1][1] = t4[3];
                ldsm4(t4, sb + 24576 + boff[p][ks]);
                b2[2 * p][0] = t4[0]; b2[2 * p][1] = t4[1];
                b2[2 * p + 1][0] = t4[2]; b2[2 * p + 1][1] = t4[3];
            }
            #pragma unroll
            for (int mi = 0; mi < 4; mi++)
                #pragma unroll
                for (int ni = 0; ni < 4; ni++) {
                    mma_f16(acc[mi][ni], ah[mi], bh[ni]);
                    mma_f16(acc[mi][ni], a2[mi], b2[ni]);
                }
        }
        __syncthreads();
    }

    const int lg = lane >> 2;
    const int lc2 = (lane & 3) * 2;
    #pragma unroll
    for (int mi = 0; mi < 4; mi++) {
        #pragma unroll
        for (int half = 0; half < 2; half++) {
            int row = row0 + wm + mi * 16 + lg + half * 8;
            #pragma unroll
            for (int ni = 0; ni < 4; ni++) {
                int col = h * 128 + wn + ni * 8 + lc2;
                float v0 = alpha * acc[mi][ni][half * 2 + 0];
                float v1 = alpha * acc[mi][ni][half * 2 + 1];
                f16 h0, c0, h1, c1;
                split2(v0, h0, c0);
                split2(v1, h1, c1);
                uint32_t hw = (uint32_t)__half_as_ushort(h0) | ((uint32_t)__half_as_ushort(h1) << 16);
                uint32_t cw = (uint32_t)__half_as_ushort(c0) | ((uint32_t)__half_as_ushort(c1) << 16);
                *reinterpret_cast<uint32_t*>(g_ATh + (size_t)row * E_DIM + col) = hw;
                *reinterpret_cast<uint32_t*>(g_ATc + (size_t)row * E_DIM + col) = cw;
            }
        }
    }
}

// fp32 -> fp16 (h, c) split
__global__ __launch_bounds__(256) void k_split(const float* __restrict__ in,
                                               f16* __restrict__ hp, f16* __restrict__ cp, int n)
{
    int i = (blockIdx.x * 256 + threadIdx.x) * 4;
    if (i >= n) return;
    float4 v = *reinterpret_cast<const float4*>(in + i);
    float vv[4] = {v.x, v.y, v.z, v.w};
    uint32_t hw[2], cw[2];
    #pragma unroll
    for (int q = 0; q < 2; q++) {
        f16 h0, c0, h1, c1;
        split2(vv[q * 2 + 0], h0, c0);
        split2(vv[q * 2 + 1], h1, c1);
        hw[q] = (uint32_t)__half_as_ushort(h0) | ((uint32_t)__half_as_ushort(h1) << 16);
        cw[q] = (uint32_t)__half_as_ushort(c0) | ((uint32_t)__half_as_ushort(c1) << 16);
    }
    *reinterpret_cast<uint2*>(hp + i) = make_uint2(hw[0], hw[1]);
    *reinterpret_cast<uint2*>(cp + i) = make_uint2(cw[0], cw[1]);
}

// KVt partial: KVt[bh][e][d] = sum_{s in split} V[b,s,h,e] * K[b,s,h,d]
__global__ __launch_bounds__(256, 2) void k_kvpart()
{
    const int split = blockIdx.x;
    const int bh = blockIdx.z;
    const int b = bh >> 4;
    const int h = bh & 15;
    const float* A  = g_V + (size_t)b * T_DIM * E_DIM + h * D_DIM;
    const float* Bk = g_K + (size_t)b * T_DIM * E_DIM + h * D_DIM;
    float* Cg = g_KVp + ((size_t)(split * 64 + bh) << 14);

    __shared__ float As[16][D_DIM];
    __shared__ float Bs[16][D_DIM];

    const int tid = threadIdx.x;
    const int lr = tid >> 5;
    const int lc = (tid & 31) << 2;
    const int ty = tid >> 4;
    const int tx = tid & 15;

    float acc[8][8];
    #pragma unroll
    for (int i = 0; i < 8; i++)
        #pragma unroll
        for (int j = 0; j < 8; j++) acc[i][j] = 0.0f;

    const int s_begin = split * (T_DIM / KVSPLIT);
    const int s_end = s_begin + (T_DIM / KVSPLIT);
    for (int s0 = s_begin; s0 < s_end; s0 += 16) {
        #pragma unroll
        for (int rr = 0; rr < 2; rr++) {
            int sdx = lr + rr * 8;
            *reinterpret_cast<float4*>(&As[sdx][lc]) =
                *reinterpret_cast<const float4*>(A + (size_t)(s0 + sdx) * E_DIM + lc);
            *reinterpret_cast<float4*>(&Bs[sdx][lc]) =
                *reinterpret_cast<const float4*>(Bk + (size_t)(s0 + sdx) * E_DIM + lc);
        }
        __syncthreads();
        #pragma unroll
        for (int k = 0; k < 16; k++) {
            float a[8], bb[8];
            *reinterpret_cast<float4*>(a)      = *reinterpret_cast<const float4*>(&As[k][ty * 8]);
            *reinterpret_cast<float4*>(a + 4)  = *reinterpret_cast<const float4*>(&As[k][ty * 8 + 4]);
            *reinterpret_cast<float4*>(bb)     = *reinterpret_cast<const float4*>(&Bs[k][tx * 8]);
            *reinterpret_cast<float4*>(bb + 4) = *reinterpret_cast<const float4*>(&Bs[k][tx * 8 + 4]);
            #pragma unroll
            for (int i = 0; i < 8; i++)
                #pragma unroll
                for (int j = 0; j < 8; j++) acc[i][j] += a[i] * bb[j];
        }
        __syncthreads();
    }

    #pragma unroll
    for (int i = 0; i < 8; i++) {
        float* Cr = Cg + (ty * 8 + i) * D_DIM + tx * 8;
        #pragma unroll
        for (int j = 0; j < 8; j += 4)
            *reinterpret_cast<float4*>(Cr + j) = make_float4(acc[i][j], acc[i][j + 1], acc[i][j + 2], acc[i][j + 3]);
    }
}

__global__ __launch_bounds__(256) void k_kvreduce()
{
    int idx = blockIdx.x * 256 + threadIdx.x;
    float sv = 0.0f;
    #pragma unroll
    for (int p = 0; p < KVSPLIT; p++) sv += g_KVp[((size_t)p << 20) + idx];
    f16 h, c;
    split2(sv, h, c);
    g_KVth[idx] = h;
    g_KVtc[idx] = c;
}

// ---------------- launch -----------------------------------------------------
extern "C" void kernel_launch(void* const* d_in, const int* in_sizes, int n_in,
                              void* d_out, int out_size)
{
    const float* x  = (const float*)d_in[0];
    const float* Wq = (const float*)d_in[1];
    const float* bq = (const float*)d_in[2];
    const float* Wk = (const float*)d_in[3];
    const float* bk = (const float*)d_in[4];
    const float* Wv = (const float*)d_in[5];
    const float* bv = (const float*)d_in[6];
    const float* Wo = (const float*)d_in[7];
    const float* bo = (const float*)d_in[8];
    float* out = (float*)d_out;

    f16 *xh, *xc, *wh, *wc, *qh, *qc, *ath, *atc;
    float *Kf, *Vf;
    cudaGetSymbolAddress((void**)&xh, g_xh);
    cudaGetSymbolAddress((void**)&xc, g_xc);
    cudaGetSymbolAddress((void**)&wh, g_Wh);
    cudaGetSymbolAddress((void**)&wc, g_Wc);
    cudaGetSymbolAddress((void**)&qh, g_Qh);
    cudaGetSymbolAddress((void**)&qc, g_Qc);
    cudaGetSymbolAddress((void**)&Kf, g_K);
    cudaGetSymbolAddress((void**)&Vf, g_V);
    cudaGetSymbolAddress((void**)&ath, g_ATh);
    cudaGetSymbolAddress((void**)&atc, g_ATc);

    cudaFuncSetAttribute(k_gemm_proj<0>, cudaFuncAttributeMaxDynamicSharedMemorySize, PG_SMEM);
    cudaFuncSetAttribute(k_gemm_proj<1>, cudaFuncAttributeMaxDynamicSharedMemorySize, PG_SMEM);
    cudaFuncSetAttribute(k_gemm_attn,    cudaFuncAttributeMaxDynamicSharedMemorySize, AT_SMEM);

    const size_t WSZ = (size_t)E_DIM * E_DIM;
    const int NX = BT_DIM * E_DIM;

    k_split<<<NX / 1024, 256>>>(x, xh, xc, NX);
    k_split<<<(int)(WSZ / 1024), 256>>>(Wq, wh + 0 * WSZ, wc + 0 * WSZ, (int)WSZ);
    k_split<<<(int)(WSZ / 1024), 256>>>(Wk, wh + 1 * WSZ, wc + 1 * WSZ, (int)WSZ);
    k_split<<<(int)(WSZ / 1024), 256>>>(Wv, wh + 2 * WSZ, wc + 2 * WSZ, (int)WSZ);
    k_split<<<(int)(WSZ / 1024), 256>>>(Wo, wh + 3 * WSZ, wc + 3 * WSZ, (int)WSZ);

    dim3 gp(E_DIM / 256, BT_DIM / 128);  // (8, 128)

    k_gemm_proj<1><<<gp, 256, PG_SMEM>>>(xh, xc, wh + 0 * WSZ, wc + 0 * WSZ, bq, nullptr, qh, qc);
    k_gemm_proj<0><<<gp, 256, PG_SMEM>>>(xh, xc, wh + 1 * WSZ, wc + 1 * WSZ, bk, Kf, nullptr, nullptr);
    k_gemm_proj<0><<<gp, 256, PG_SMEM>>>(xh, xc, wh + 2 * WSZ, wc + 2 * WSZ, bv, Vf, nullptr, nullptr);

    k_kvpart<<<dim3(KVSPLIT, 1, 64), 256>>>();
    k_kvreduce<<<(64 * D_DIM * D_DIM) / 256, 256>>>();

    k_gemm_attn<<<dim3(1, BT_DIM / 128, H_DIM), 256, AT_SMEM>>>();

    k_gemm_proj<0><<<gp, 256, PG_SMEM>>>(ath, atc, wh + 3 * WSZ, wc + 3 * WSZ, bo, out, nullptr, nullptr);
}

// round 7
// speedup vs baseline: 4.3597x; 1.2159x over previous
#include <cuda_runtime.h>
#include <cuda_fp16.h>
#include <cstdint>

#define B_DIM 4
#define T_DIM 4096
#define E_DIM 2048
#define H_DIM 16
#define D_DIM 128
#define BT_DIM 16384
#define KVSPLIT 8

typedef __half f16;

// ---------------- scratch (device globals; no allocations allowed) ----------
// pair convention: h = fp16(v); c = fp16((h + 32*(v-h)) / sqrt(31))
// GEMM: acc = sum h_a h_b + sum c_a c_b ; result = (31/32) * acc
__device__ f16 g_xh[(size_t)BT_DIM * E_DIM];
__device__ f16 g_xc[(size_t)BT_DIM * E_DIM];
__device__ f16 g_Wh[4][(size_t)E_DIM * E_DIM];
__device__ f16 g_Wc[4][(size_t)E_DIM * E_DIM];
__device__ f16 g_Qh[(size_t)BT_DIM * E_DIM];
__device__ f16 g_Qc[(size_t)BT_DIM * E_DIM];
// transposed K/V pair planes: [b][e][t], t contiguous (K-major for KV gemm)
__device__ f16 g_KTh[(size_t)B_DIM * E_DIM * T_DIM];
__device__ f16 g_KTc[(size_t)B_DIM * E_DIM * T_DIM];
__device__ f16 g_VTh[(size_t)B_DIM * E_DIM * T_DIM];
__device__ f16 g_VTc[(size_t)B_DIM * E_DIM * T_DIM];
__device__ f16 g_ATh[(size_t)BT_DIM * E_DIM];
__device__ f16 g_ATc[(size_t)BT_DIM * E_DIM];
__device__ float g_KVp[(size_t)KVSPLIT * 64 * D_DIM * D_DIM];
__device__ f16 g_KVth[64 * D_DIM * D_DIM];
__device__ f16 g_KVtc[64 * D_DIM * D_DIM];

#define SPLIT_S     32.0f
#define INV_SQRT31  0.17960530202677491f
#define COMB_SCALE  0.96875f          // 31/32

// ---------------- helpers ----------------------------------------------------
__device__ __forceinline__ uint32_t smem_u32(const void* p) {
    uint32_t a;
    asm("{ .reg .u64 t; cvta.to.shared.u64 t, %1; cvt.u32.u64 %0, t; }" : "=r"(a) : "l"(p));
    return a;
}
__device__ __forceinline__ void cp_async16(uint32_t sdst, const void* gsrc) {
    asm volatile("cp.async.cg.shared.global [%0], [%1], 16;" :: "r"(sdst), "l"(gsrc) : "memory");
}
#define CP_COMMIT() asm volatile("cp.async.commit_group;" ::: "memory")
#define CP_WAIT1()  asm volatile("cp.async.wait_group 1;" ::: "memory")
#define CP_WAIT2()  asm volatile("cp.async.wait_group 2;" ::: "memory")

__device__ __forceinline__ void ldsm4(uint32_t* r, uint32_t a) {
    asm volatile("ldmatrix.sync.aligned.m8n8.x4.shared.b16 {%0,%1,%2,%3}, [%4];"
                 : "=r"(r[0]), "=r"(r[1]), "=r"(r[2]), "=r"(r[3]) : "r"(a));
}
__device__ __forceinline__ void mma_f16(float* c, const uint32_t* a, const uint32_t* b) {
    asm volatile(
        "mma.sync.aligned.m16n8k16.row.col.f32.f16.f16.f32 "
        "{%0,%1,%2,%3}, {%4,%5,%6,%7}, {%8,%9}, {%0,%1,%2,%3};"
        : "+f"(c[0]), "+f"(c[1]), "+f"(c[2]), "+f"(c[3])
        : "r"(a[0]), "r"(a[1]), "r"(a[2]), "r"(a[3]), "r"(b[0]), "r"(b[1]));
}
__device__ __forceinline__ void split2(float v, f16& h, f16& c) {
    h = __float2half_rn(v);
    float lo = v - __half2float(h);
    c = __float2half_rn((__half2float(h) + SPLIT_S * lo) * INV_SQRT31);
}
__device__ __forceinline__ uint32_t packw(f16 h, f16 c) {
    return (uint32_t)__half_as_ushort(h) | ((uint32_t)__half_as_ushort(c) << 16);
}

// tile loader: 128B rows (64 f16), 8x16B chunks, swizzle chunk c^(r&7)
__device__ __forceinline__ void load_rows64(uint32_t sdst, const f16* __restrict__ g,
                                            int row0, int col0, int ld, int iters) {
    const int t = threadIdx.x;
    #pragma unroll 8
    for (int i = 0; i < iters; i++) {
        int idx = t + i * 256;
        int r = idx >> 3, c = idx & 7;
        const f16* src = g + (size_t)(row0 + r) * ld + col0 + c * 8;
        cp_async16(sdst + r * 128 + ((c ^ (r & 7)) << 4), src);
    }
}

// ---------------- big GEMM: CTA 128x256, warp 64x64, BK=64, 2 stages ---------
#define PG_AH 0
#define PG_AC 16384
#define PG_BH 32768
#define PG_BC 65536
#define PG_STAGE 98304
#define PG_SMEM  (2 * PG_STAGE)

// OUT_MODE 0: fp32 row-major (+bias)
// OUT_MODE 1: (h,c) pair row-major (+bias)
// OUT_MODE 2: (h,c) pair TRANSPOSED [b][e][t] (+bias) via smem staging
template <int OUT_MODE>
__global__ __launch_bounds__(256, 1) void k_gemm_proj(
    const f16* __restrict__ Ah, const f16* __restrict__ Ac,
    const f16* __restrict__ Bh, const f16* __restrict__ Bc,
    const float* __restrict__ bias,
    float* __restrict__ Cf, f16* __restrict__ C1, f16* __restrict__ C2)
{
    extern __shared__ __align__(1024) char smdyn[];
    const uint32_t sbase = smem_u32(smdyn);
    const int tid = threadIdx.x;
    const int wid = tid >> 5, lane = tid & 31;
    const int wm = (wid & 1) * 64;
    const int wn = (wid >> 1) * 64;
    const int row0 = blockIdx.y * 128;
    const int n0 = blockIdx.x * 256;

    // ldsm base addrs at ks=0; per-ks address = base ^ (ks<<5)
    uint32_t abase[4];
    #pragma unroll
    for (int mi = 0; mi < 4; mi++) {
        int r = wm + mi * 16 + (lane & 15);
        int hi = lane >> 4;
        abase[mi] = r * 128 + ((hi ^ (r & 7)) << 4);
    }
    uint32_t bbase[4];
    #pragma unroll
    for (int p = 0; p < 4; p++) {
        int g2 = lane >> 3;
        int r = wn + p * 16 + ((g2 >> 1) << 3) + (lane & 7);
        bbase[p] = r * 128 + (((g2 & 1) ^ (r & 7)) << 4);
    }

    float acc[4][8][4];
    #pragma unroll
    for (int mi = 0; mi < 4; mi++)
        #pragma unroll
        for (int ni = 0; ni < 8; ni++)
            #pragma unroll
            for (int q = 0; q < 4; q++) acc[mi][ni][q] = 0.0f;

    #pragma unroll
    for (int i = 0; i < 2; i++) {
        uint32_t sb = sbase + i * PG_STAGE;
        int k0 = i * 64;
        load_rows64(sb + PG_AH, Ah, row0, k0, E_DIM, 4);
        load_rows64(sb + PG_AC, Ac, row0, k0, E_DIM, 4);
        load_rows64(sb + PG_BH, Bh, n0, k0, E_DIM, 8);
        load_rows64(sb + PG_BC, Bc, n0, k0, E_DIM, 8);
        CP_COMMIT();
    }

    for (int c = 0; c < 32; c++) {
        CP_WAIT1();
        __syncthreads();
        const uint32_t sb = sbase + (c & 1) * PG_STAGE;
        #pragma unroll
        for (int ks = 0; ks < 4; ks++) {
            const uint32_t kx = ks << 5;
            uint32_t ah[4][4], a2[4][4], bh[8][2], b2[8][2];
            #pragma unroll
            for (int mi = 0; mi < 4; mi++) {
                ldsm4(ah[mi], sb + PG_AH + (abase[mi] ^ kx));
                ldsm4(a2[mi], sb + PG_AC + (abase[mi] ^ kx));
            }
            #pragma unroll
            for (int p = 0; p < 4; p++) {
                uint32_t t4[4];
                ldsm4(t4, sb + PG_BH + (bbase[p] ^ kx));
                bh[2 * p][0] = t4[0]; bh[2 * p][1] = t4[1];
                bh[2 * p + 1][0] = t4[2]; bh[2 * p + 1][1] = t4[3];
                ldsm4(t4, sb + PG_BC + (bbase[p] ^ kx));
                b2[2 * p][0] = t4[0]; b2[2 * p][1] = t4[1];
                b2[2 * p + 1][0] = t4[2]; b2[2 * p + 1][1] = t4[3];
            }
            #pragma unroll
            for (int mi = 0; mi < 4; mi++)
                #pragma unroll
                for (int ni = 0; ni < 8; ni++) {
                    mma_f16(acc[mi][ni], ah[mi], bh[ni]);
                    mma_f16(acc[mi][ni], a2[mi], b2[ni]);
                }
        }
        __syncthreads();
        if (c + 2 < 32) {
            uint32_t sb2 = sbase + (c & 1) * PG_STAGE;
            int k0 = (c + 2) * 64;
            load_rows64(sb2 + PG_AH, Ah, row0, k0, E_DIM, 4);
            load_rows64(sb2 + PG_AC, Ac, row0, k0, E_DIM, 4);
            load_rows64(sb2 + PG_BH, Bh, n0, k0, E_DIM, 8);
            load_rows64(sb2 + PG_BC, Bc, n0, k0, E_DIM, 8);
        }
        CP_COMMIT();
    }

    const int lg = lane >> 2;
    const int lc2 = (lane & 3) * 2;

    if (OUT_MODE == 2) {
        // stage packed (h|c<<16) words at [t][e], pitch 257 words, then write
        // transposed coalesced to C1/C2 = [b][e][t] planes.
        uint32_t* buf = reinterpret_cast<uint32_t*>(smdyn);
        const int P = 257;
        #pragma unroll
        for (int mi = 0; mi < 4; mi++) {
            #pragma unroll
            for (int half = 0; half < 2; half++) {
                int t = wm + mi * 16 + lg + half * 8;
                #pragma unroll
                for (int ni = 0; ni < 8; ni++) {
                    int j = wn + ni * 8 + lc2;
                    float v0 = COMB_SCALE * acc[mi][ni][half * 2 + 0] + bias[n0 + j];
                    float v1 = COMB_SCALE * acc[mi][ni][half * 2 + 1] + bias[n0 + j + 1];
                    f16 h0, c0, h1, c1;
                    split2(v0, h0, c0);
                    split2(v1, h1, c1);
                    buf[t * P + j] = packw(h0, c0);
                    buf[t * P + j + 1] = packw(h1, c1);
                }
            }
        }
        __syncthreads();
        const int b = row0 >> 12;
        const int t0 = row0 & 4095;
        #pragma unroll 4
        for (int pass = 0; pass < 16; pass++) {
            int j = pass * 16 + (tid >> 4);
            int tq = (tid & 15) * 8;
            uint32_t hv[4], cv[4];
            #pragma unroll
            for (int q = 0; q < 4; q++) {
                uint32_t w0 = buf[(tq + 2 * q) * P + j];
                uint32_t w1 = buf[(tq + 2 * q + 1) * P + j];
                hv[q] = (w0 & 0xFFFFu) | (w1 << 16);
                cv[q] = (w0 >> 16) | (w1 & 0xFFFF0000u);
            }
            size_t base = ((size_t)b * E_DIM + (n0 + j)) * T_DIM + t0 + tq;
            *reinterpret_cast<uint4*>(C1 + base) = make_uint4(hv[0], hv[1], hv[2], hv[3]);
            *reinterpret_cast<uint4*>(C2 + base) = make_uint4(cv[0], cv[1], cv[2], cv[3]);
        }
    } else {
        #pragma unroll
        for (int mi = 0; mi < 4; mi++) {
            #pragma unroll
            for (int half = 0; half < 2; half++) {
                int row = row0 + wm + mi * 16 + lg + half * 8;
                #pragma unroll
                for (int ni = 0; ni < 8; ni++) {
                    int col = n0 + wn + ni * 8 + lc2;
                    float v0 = COMB_SCALE * acc[mi][ni][half * 2 + 0] + bias[col];
                    float v1 = COMB_SCALE * acc[mi][ni][half * 2 + 1] + bias[col + 1];
                    if (OUT_MODE == 0) {
                        *reinterpret_cast<float2*>(Cf + (size_t)row * E_DIM + col) = make_float2(v0, v1);
                    } else {
                        f16 h0, c0, h1, c1;
                        split2(v0, h0, c0);
                        split2(v1, h1, c1);
                        *reinterpret_cast<uint32_t*>(C1 + (size_t)row * E_DIM + col) =
                            (uint32_t)__half_as_ushort(h0) | ((uint32_t)__half_as_ushort(h1) << 16);
                        *reinterpret_cast<uint32_t*>(C2 + (size_t)row * E_DIM + col) =
                            (uint32_t)__half_as_ushort(c0) | ((uint32_t)__half_as_ushort(c1) << 16);
                    }
                }
            }
        }
    }
}

// ---------------- KV gemm: CTA 128x128 (e x d), warp 64x32, split-K ----------
#define KV_AH 0
#define KV_AC 16384
#define KV_BH 32768
#define KV_BC 49152
#define KV_STAGE 65536
#define KV_SMEM  (2 * KV_STAGE)

__global__ __launch_bounds__(256, 1) void k_kv_mma()
{
    const int split = blockIdx.x;
    const int bh = blockIdx.z;
    const int b = bh >> 4;
    const int h = bh & 15;
    const size_t hb = ((size_t)b * E_DIM + h * 128) * T_DIM;
    const f16* Ah = g_VTh + hb;   // rows e, K-major over t
    const f16* Ac = g_VTc + hb;
    const f16* Bh = g_KTh + hb;   // rows d
    const f16* Bc = g_KTc + hb;
    const int acol = split * (T_DIM / KVSPLIT);   // 512

    extern __shared__ __align__(1024) char smdyn[];
    const uint32_t sbase = smem_u32(smdyn);
    const int tid = threadIdx.x;
    const int wid = tid >> 5, lane = tid & 31;
    const int wm = (wid & 1) * 64;
    const int wn = (wid >> 1) * 32;

    uint32_t abase[4];
    #pragma unroll
    for (int mi = 0; mi < 4; mi++) {
        int r = wm + mi * 16 + (lane & 15);
        int hi = lane >> 4;
        abase[mi] = r * 128 + ((hi ^ (r & 7)) << 4);
    }
    uint32_t bbase[2];
    #pragma unroll
    for (int p = 0; p < 2; p++) {
        int g2 = lane >> 3;
        int r = wn + p * 16 + ((g2 >> 1) << 3) + (lane & 7);
        bbase[p] = r * 128 + (((g2 & 1) ^ (r & 7)) << 4);
    }

    float acc[4][4][4];
    #pragma unroll
    for (int mi = 0; mi < 4; mi++)
        #pragma unroll
        for (int ni = 0; ni < 4; ni++)
            #pragma unroll
            for (int q = 0; q < 4; q++) acc[mi][ni][q] = 0.0f;

    #pragma unroll
    for (int i = 0; i < 2; i++) {
        uint32_t sb = sbase + i * KV_STAGE;
        int k0 = acol + i * 64;
        load_rows64(sb + KV_AH, Ah, 0, k0, T_DIM, 4);
        load_rows64(sb + KV_AC, Ac, 0, k0, T_DIM, 4);
        load_rows64(sb + KV_BH, Bh, 0, k0, T_DIM, 4);
        load_rows64(sb + KV_BC, Bc, 0, k0, T_DIM, 4);
        CP_COMMIT();
    }

    const int NC = (T_DIM / KVSPLIT) / 64;   // 8
    for (int c = 0; c < NC; c++) {
        CP_WAIT1();
        __syncthreads();
        const uint32_t sb = sbase + (c & 1) * KV_STAGE;
        #pragma unroll
        for (int ks = 0; ks < 4; ks++) {
            const uint32_t kx = ks << 5;
            uint32_t ah[4][4], a2[4][4], bh[4][2], b2[4][2];
            #pragma unroll
            for (int mi = 0; mi < 4; mi++) {
                ldsm4(ah[mi], sb + KV_AH + (abase[mi] ^ kx));
                ldsm4(a2[mi], sb + KV_AC + (abase[mi] ^ kx));
            }
            #pragma unroll
            for (int p = 0; p < 2; p++) {
                uint32_t t4[4];
                ldsm4(t4, sb + KV_BH + (bbase[p] ^ kx));
                bh[2 * p][0] = t4[0]; bh[2 * p][1] = t4[1];
                bh[2 * p + 1][0] = t4[2]; bh[2 * p + 1][1] = t4[3];
                ldsm4(t4, sb + KV_BC + (bbase[p] ^ kx));
                b2[2 * p][0] = t4[0]; b2[2 * p][1] = t4[1];
                b2[2 * p + 1][0] = t4[2]; b2[2 * p + 1][1] = t4[3];
            }
            #pragma unroll
            for (int mi = 0; mi < 4; mi++)
                #pragma unroll
                for (int ni = 0; ni < 4; ni++) {
                    mma_f16(acc[mi][ni], ah[mi], bh[ni]);
                    mma_f16(acc[mi][ni], a2[mi], b2[ni]);
                }
        }
        __syncthreads();
        if (c + 2 < NC) {
            uint32_t sb2 = sbase + (c & 1) * KV_STAGE;
            int k0 = acol + (c + 2) * 64;
            load_rows64(sb2 + KV_AH, Ah, 0, k0, T_DIM, 4);
            load_rows64(sb2 + KV_AC, Ac, 0, k0, T_DIM, 4);
            load_rows64(sb2 + KV_BH, Bh, 0, k0, T_DIM, 4);
            load_rows64(sb2 + KV_BC, Bc, 0, k0, T_DIM, 4);
        }
        CP_COMMIT();
    }

    float* Cg = g_KVp + ((size_t)(split * 64 + bh) << 14);
    const int lg = lane >> 2;
    const int lc2 = (lane & 3) * 2;
    #pragma unroll
    for (int mi = 0; mi < 4; mi++)
        #pragma unroll
        for (int half = 0; half < 2; half++) {
            int row = wm + mi * 16 + lg + half * 8;   // e
            #pragma unroll
            for (int ni = 0; ni < 4; ni++) {
                int col = wn + ni * 8 + lc2;          // d
                *reinterpret_cast<float2*>(Cg + row * D_DIM + col) =
                    make_float2(COMB_SCALE * acc[mi][ni][half * 2 + 0],
                                COMB_SCALE * acc[mi][ni][half * 2 + 1]);
            }
        }
}

// ---------------- attn GEMM: CTA 128x128, K=128 (unchanged from R6) ----------
#define AT_STAGE 32768
#define AT_SMEM  (3 * AT_STAGE)

__device__ __forceinline__ void load_tile128(uint32_t sdst, const f16* __restrict__ g,
                                             int row0, int col0, int ld) {
    const int t = threadIdx.x;
    #pragma unroll
    for (int i = 0; i < 2; i++) {
        int idx = t + i * 256;
        int r = idx >> 2, c = idx & 3;
        const f16* src = g + (size_t)(row0 + r) * ld + col0 + c * 8;
        uint32_t off = r * 64 + ((c ^ ((r >> 1) & 3)) << 4);
        cp_async16(sdst + off, src);
    }
}

__global__ __launch_bounds__(256) void k_gemm_attn()
{
    const float alpha = 0.08838834764831845f * COMB_SCALE;
    const int h = blockIdx.z;
    const int row0 = blockIdx.y * 128;
    const int b = row0 >> 12;
    const int bh = (b << 4) + h;
    const f16* Ah = g_Qh;
    const f16* Ac = g_Qc;
    const f16* Bh = g_KVth + ((size_t)bh << 14);
    const f16* Bc = g_KVtc + ((size_t)bh << 14);
    const int acol = h * 128;

    extern __shared__ __align__(1024) char smdyn[];
    const uint32_t sbase = smem_u32(smdyn);
    const int tid = threadIdx.x;
    const int wid = tid >> 5, lane = tid & 31;
    const int wm = (wid & 1) * 64;
    const int wn = (wid >> 1) * 32;

    uint32_t aoff[4][2];
    #pragma unroll
    for (int mi = 0; mi < 4; mi++) {
        int r = wm + mi * 16 + (lane & 15);
        #pragma unroll
        for (int ks = 0; ks < 2; ks++) {
            int kc = ks * 2 + (lane >> 4);
            aoff[mi][ks] = r * 64 + ((kc ^ ((r >> 1) & 3)) << 4);
        }
    }
    uint32_t boff[2][2];
    #pragma unroll
    for (int p = 0; p < 2; p++) {
        int g2 = lane >> 3;
        int r = wn + p * 16 + ((g2 >> 1) << 3) + (lane & 7);
        #pragma unroll
        for (int ks = 0; ks < 2; ks++) {
            int kc = ks * 2 + (g2 & 1);
            boff[p][ks] = r * 64 + ((kc ^ ((r >> 1) & 3)) << 4);
        }
    }

    float acc[4][4][4];
    #pragma unroll
    for (int mi = 0; mi < 4; mi++)
        #pragma unroll
        for (int ni = 0; ni < 4; ni++)
            #pragma unroll
            for (int q = 0; q < 4; q++) acc[mi][ni][q] = 0.0f;

    #pragma unroll
    for (int i = 0; i < 2; i++) {
        uint32_t sb = sbase + i * AT_STAGE;
        int k0 = i * 32;
        load_tile128(sb + 0,     Ah, row0, acol + k0, E_DIM);
        load_tile128(sb + 8192,  Ac, row0, acol + k0, E_DIM);
        load_tile128(sb + 16384, Bh, 0, k0, D_DIM);
        load_tile128(sb + 24576, Bc, 0, k0, D_DIM);
        CP_COMMIT();
    }

    for (int c = 0; c < 4; c++) {
        if (c + 2 < 4) {
            uint32_t sb = sbase + ((c + 2) % 3) * AT_STAGE;
            int k0 = (c + 2) * 32;
            load_tile128(sb + 0,     Ah, row0, acol + k0, E_DIM);
            load_tile128(sb + 8192,  Ac, row0, acol + k0, E_DIM);
            load_tile128(sb + 16384, Bh, 0, k0, D_DIM);
            load_tile128(sb + 24576, Bc, 0, k0, D_DIM);
        }
        CP_COMMIT();
        CP_WAIT2();
        __syncthreads();

        const uint32_t sb = sbase + (c % 3) * AT_STAGE;
        #pragma unroll
        for (int ks = 0; ks < 2; ks++) {
            uint32_t ah[4][4], a2[4][4], bh[4][2], b2[4][2];
            #pragma unroll
            for (int mi = 0; mi < 4; mi++) {
                ldsm4(ah[mi], sb + aoff[mi][ks]);
                ldsm4(a2[mi], sb + 8192 + aoff[mi][ks]);
            }
            #pragma unroll
            for (int p = 0; p < 2; p++) {
                uint32_t t4[4];
                ldsm4(t4, sb + 16384 + boff[p][ks]);
                bh[2 * p][0] = t4[0]; bh[2 * p][1] = t4[1];
                bh[2 * p + 1][0] = t4[2]; bh[2 * p + 1][1] = t4[3];
                ldsm4(t4, sb + 24576 + boff[p][ks]);
                b2[2 * p][0] = t4[0]; b2[2 * p][1] = t4[1];
                b2[2 * p + 1][0] = t4[2]; b2[2 * p + 1][1] = t4[3];
            }
            #pragma unroll
            for (int mi = 0; mi < 4; mi++)
                #pragma unroll
                for (int ni = 0; ni < 4; ni++) {
                    mma_f16(acc[mi][ni], ah[mi], bh[ni]);
                    mma_f16(acc[mi][ni], a2[mi], b2[ni]);
                }
        }
        __syncthreads();
    }

    const int lg = lane >> 2;
    const int lc2 = (lane & 3) * 2;
    #pragma unroll
    for (int mi = 0; mi < 4; mi++) {
        #pragma unroll
        for (int half = 0; half < 2; half++) {
            int row = row0 + wm + mi * 16 + lg + half * 8;
            #pragma unroll
            for (int ni = 0; ni < 4; ni++) {
                int col = h * 128 + wn + ni * 8 + lc2;
                float v0 = alpha * acc[mi][ni][half * 2 + 0];
                float v1 = alpha * acc[mi][ni][half * 2 + 1];
                f16 h0, c0, h1, c1;
                split2(v0, h0, c0);
                split2(v1, h1, c1);
                *reinterpret_cast<uint32_t*>(g_ATh + (size_t)row * E_DIM + col) =
                    (uint32_t)__half_as_ushort(h0) | ((uint32_t)__half_as_ushort(h1) << 16);
                *reinterpret_cast<uint32_t*>(g_ATc + (size_t)row * E_DIM + col) =
                    (uint32_t)__half_as_ushort(c0) | ((uint32_t)__half_as_ushort(c1) << 16);
            }
        }
    }
}

// fp32 -> fp16 (h, c) split
__global__ __launch_bounds__(256) void k_split(const float* __restrict__ in,
                                               f16* __restrict__ hp, f16* __restrict__ cp, int n)
{
    int i = (blockIdx.x * 256 + threadIdx.x) * 4;
    if (i >= n) return;
    float4 v = *reinterpret_cast<const float4*>(in + i);
    float vv[4] = {v.x, v.y, v.z, v.w};
    uint32_t hw[2], cw[2];
    #pragma unroll
    for (int q = 0; q < 2; q++) {
        f16 h0, c0, h1, c1;
        split2(vv[q * 2 + 0], h0, c0);
        split2(vv[q * 2 + 1], h1, c1);
        hw[q] = (uint32_t)__half_as_ushort(h0) | ((uint32_t)__half_as_ushort(h1) << 16);
        cw[q] = (uint32_t)__half_as_ushort(c0) | ((uint32_t)__half_as_ushort(c1) << 16);
    }
    *reinterpret_cast<uint2*>(hp + i) = make_uint2(hw[0], hw[1]);
    *reinterpret_cast<uint2*>(cp + i) = make_uint2(cw[0], cw[1]);
}

__global__ __launch_bounds__(256) void k_kvreduce()
{
    int idx = blockIdx.x * 256 + threadIdx.x;
    float sv = 0.0f;
    #pragma unroll
    for (int p = 0; p < KVSPLIT; p++) sv += g_KVp[((size_t)p << 20) + idx];
    f16 h, c;
    split2(sv, h, c);
    g_KVth[idx] = h;
    g_KVtc[idx] = c;
}

// ---------------- launch -----------------------------------------------------
extern "C" void kernel_launch(void* const* d_in, const int* in_sizes, int n_in,
                              void* d_out, int out_size)
{
    const float* x  = (const float*)d_in[0];
    const float* Wq = (const float*)d_in[1];
    const float* bq = (const float*)d_in[2];
    const float* Wk = (const float*)d_in[3];
    const float* bk = (const float*)d_in[4];
    const float* Wv = (const float*)d_in[5];
    const float* bv = (const float*)d_in[6];
    const float* Wo = (const float*)d_in[7];
    const float* bo = (const float*)d_in[8];
    float* out = (float*)d_out;

    f16 *xh, *xc, *wh, *wc, *qh, *qc, *ath, *atc;
    f16 *kth, *ktc, *vth, *vtc;
    cudaGetSymbolAddress((void**)&xh, g_xh);
    cudaGetSymbolAddress((void**)&xc, g_xc);
    cudaGetSymbolAddress((void**)&wh, g_Wh);
    cudaGetSymbolAddress((void**)&wc, g_Wc);
    cudaGetSymbolAddress((void**)&qh, g_Qh);
    cudaGetSymbolAddress((void**)&qc, g_Qc);
    cudaGetSymbolAddress((void**)&kth, g_KTh);
    cudaGetSymbolAddress((void**)&ktc, g_KTc);
    cudaGetSymbolAddress((void**)&vth, g_VTh);
    cudaGetSymbolAddress((void**)&vtc, g_VTc);
    cudaGetSymbolAddress((void**)&ath, g_ATh);
    cudaGetSymbolAddress((void**)&atc, g_ATc);

    cudaFuncSetAttribute(k_gemm_proj<0>, cudaFuncAttributeMaxDynamicSharedMemorySize, PG_SMEM);
    cudaFuncSetAttribute(k_gemm_proj<1>, cudaFuncAttributeMaxDynamicSharedMemorySize, PG_SMEM);
    cudaFuncSetAttribute(k_gemm_proj<2>, cudaFuncAttributeMaxDynamicSharedMemorySize, PG_SMEM);
    cudaFuncSetAttribute(k_kv_mma,       cudaFuncAttributeMaxDynamicSharedMemorySize, KV_SMEM);
    cudaFuncSetAttribute(k_gemm_attn,    cudaFuncAttributeMaxDynamicSharedMemorySize, AT_SMEM);

    const size_t WSZ = (size_t)E_DIM * E_DIM;
    const int NX = BT_DIM * E_DIM;

    k_split<<<NX / 1024, 256>>>(x, xh, xc, NX);
    k_split<<<(int)(WSZ / 1024), 256>>>(Wq, wh + 0 * WSZ, wc + 0 * WSZ, (int)WSZ);
    k_split<<<(int)(WSZ / 1024), 256>>>(Wk, wh + 1 * WSZ, wc + 1 * WSZ, (int)WSZ);
    k_split<<<(int)(WSZ / 1024), 256>>>(Wv, wh + 2 * WSZ, wc + 2 * WSZ, (int)WSZ);
    k_split<<<(int)(WSZ / 1024), 256>>>(Wo, wh + 3 * WSZ, wc + 3 * WSZ, (int)WSZ);

    dim3 gp(E_DIM / 256, BT_DIM / 128);  // (8, 128)

    k_gemm_proj<1><<<gp, 256, PG_SMEM>>>(xh, xc, wh + 0 * WSZ, wc + 0 * WSZ, bq, nullptr, qh, qc);
    k_gemm_proj<2><<<gp, 256, PG_SMEM>>>(xh, xc, wh + 1 * WSZ, wc + 1 * WSZ, bk, nullptr, kth, ktc);
    k_gemm_proj<2><<<gp, 256, PG_SMEM>>>(xh, xc, wh + 2 * WSZ, wc + 2 * WSZ, bv, nullptr, vth, vtc);

    k_kv_mma<<<dim3(KVSPLIT, 1, 64), 256, KV_SMEM>>>();
    k_kvreduce<<<(64 * D_DIM * D_DIM) / 256, 256>>>();

    k_gemm_attn<<<dim3(1, BT_DIM / 128, H_DIM), 256, AT_SMEM>>>();

    k_gemm_proj<0><<<gp, 256, PG_SMEM>>>(ath, atc, wh + 3 * WSZ, wc + 3 * WSZ, bo, out, nullptr, nullptr);
}

// round 8
// speedup vs baseline: 8.2087x; 1.8829x over previous
#include <cuda_runtime.h>
#include <cuda_fp16.h>
#include <cstdint>

#define B_DIM 4
#define T_DIM 4096
#define E_DIM 2048
#define H_DIM 16
#define D_DIM 128
#define BT_DIM 16384
#define KVSPLIT 8

typedef __half f16;

// ---------------- scratch (device globals; no allocations allowed) ----------
__device__ f16 g_xh[(size_t)BT_DIM * E_DIM];
__device__ f16 g_Wh[4][(size_t)E_DIM * E_DIM];
__device__ f16 g_Qh[(size_t)BT_DIM * E_DIM];
// transposed K/V planes: [b][e][t], t contiguous (K-major for KV gemm)
__device__ f16 g_KTh[(size_t)B_DIM * E_DIM * T_DIM];
__device__ f16 g_VTh[(size_t)B_DIM * E_DIM * T_DIM];
__device__ f16 g_ATh[(size_t)BT_DIM * E_DIM];
__device__ float g_KVp[(size_t)KVSPLIT * 64 * D_DIM * D_DIM];
__device__ f16 g_KVth[64 * D_DIM * D_DIM];

// ---------------- helpers ----------------------------------------------------
__device__ __forceinline__ uint32_t smem_u32(const void* p) {
    uint32_t a;
    asm("{ .reg .u64 t; cvta.to.shared.u64 t, %1; cvt.u32.u64 %0, t; }" : "=r"(a) : "l"(p));
    return a;
}
__device__ __forceinline__ void cp_async16(uint32_t sdst, const void* gsrc) {
    asm volatile("cp.async.cg.shared.global [%0], [%1], 16;" :: "r"(sdst), "l"(gsrc) : "memory");
}
#define CP_COMMIT() asm volatile("cp.async.commit_group;" ::: "memory")
#define CP_WAIT1()  asm volatile("cp.async.wait_group 1;" ::: "memory")
#define CP_WAIT2()  asm volatile("cp.async.wait_group 2;" ::: "memory")

__device__ __forceinline__ void ldsm4(uint32_t* r, uint32_t a) {
    asm volatile("ldmatrix.sync.aligned.m8n8.x4.shared.b16 {%0,%1,%2,%3}, [%4];"
                 : "=r"(r[0]), "=r"(r[1]), "=r"(r[2]), "=r"(r[3]) : "r"(a));
}
__device__ __forceinline__ void mma_f16(float* c, const uint32_t* a, const uint32_t* b) {
    asm volatile(
        "mma.sync.aligned.m16n8k16.row.col.f32.f16.f16.f32 "
        "{%0,%1,%2,%3}, {%4,%5,%6,%7}, {%8,%9}, {%0,%1,%2,%3};"
        : "+f"(c[0]), "+f"(c[1]), "+f"(c[2]), "+f"(c[3])
        : "r"(a[0]), "r"(a[1]), "r"(a[2]), "r"(a[3]), "r"(b[0]), "r"(b[1]));
}

// tile loader: 128B rows (64 f16), 8x16B chunks, swizzle chunk c^(r&7)
__device__ __forceinline__ void load_rows64(uint32_t sdst, const f16* __restrict__ g,
                                            int row0, int col0, int ld, int iters) {
    const int t = threadIdx.x;
    #pragma unroll 8
    for (int i = 0; i < iters; i++) {
        int idx = t + i * 256;
        int r = idx >> 3, c = idx & 7;
        const f16* src = g + (size_t)(row0 + r) * ld + col0 + c * 8;
        cp_async16(sdst + r * 128 + ((c ^ (r & 7)) << 4), src);
    }
}

// ---------------- big GEMM: CTA 128x256, warp 64x64, BK=128, 2 stages --------
// stage layout: A sub0 @0 (16KB), A sub1 @16K, B sub0 @32K (32KB), B sub1 @64K
#define PG_A0 0
#define PG_A1 16384
#define PG_B0 32768
#define PG_B1 65536
#define PG_STAGE 98304
#define PG_SMEM  (2 * PG_STAGE)

// OUT_MODE 0: fp32 row-major (+bias)
// OUT_MODE 1: f16 row-major (+bias)
// OUT_MODE 2: f16 TRANSPOSED [b][e][t] (+bias) via smem staging
template <int OUT_MODE>
__global__ __launch_bounds__(256, 1) void k_gemm_proj(
    const f16* __restrict__ Ah, const f16* __restrict__ Bh,
    const float* __restrict__ bias,
    float* __restrict__ Cf, f16* __restrict__ C1)
{
    extern __shared__ __align__(1024) char smdyn[];
    const uint32_t sbase = smem_u32(smdyn);
    const int tid = threadIdx.x;
    const int wid = tid >> 5, lane = tid & 31;
    const int wm = (wid & 1) * 64;
    const int wn = (wid >> 1) * 64;
    const int row0 = blockIdx.y * 128;
    const int n0 = blockIdx.x * 256;

    uint32_t abase[4];
    #pragma unroll
    for (int mi = 0; mi < 4; mi++) {
        int r = wm + mi * 16 + (lane & 15);
        int hi = lane >> 4;
        abase[mi] = r * 128 + ((hi ^ (r & 7)) << 4);
    }
    uint32_t bbase[4];
    #pragma unroll
    for (int p = 0; p < 4; p++) {
        int g2 = lane >> 3;
        int r = wn + p * 16 + ((g2 >> 1) << 3) + (lane & 7);
        bbase[p] = r * 128 + (((g2 & 1) ^ (r & 7)) << 4);
    }

    float acc[4][8][4];
    #pragma unroll
    for (int mi = 0; mi < 4; mi++)
        #pragma unroll
        for (int ni = 0; ni < 8; ni++)
            #pragma unroll
            for (int q = 0; q < 4; q++) acc[mi][ni][q] = 0.0f;

    #pragma unroll
    for (int i = 0; i < 2; i++) {
        uint32_t sb = sbase + i * PG_STAGE;
        int k0 = i * 128;
        load_rows64(sb + PG_A0, Ah, row0, k0,      E_DIM, 4);
        load_rows64(sb + PG_A1, Ah, row0, k0 + 64, E_DIM, 4);
        load_rows64(sb + PG_B0, Bh, n0,   k0,      E_DIM, 8);
        load_rows64(sb + PG_B1, Bh, n0,   k0 + 64, E_DIM, 8);
        CP_COMMIT();
    }

    const int NC = E_DIM / 128;   // 16
    for (int c = 0; c < NC; c++) {
        CP_WAIT1();
        __syncthreads();
        const uint32_t sb = sbase + (c & 1) * PG_STAGE;
        #pragma unroll
        for (int ks = 0; ks < 8; ks++) {
            const uint32_t asub = sb + ((ks & 4) ? PG_A1 : PG_A0);
            const uint32_t bsub = sb + ((ks & 4) ? PG_B1 : PG_B0);
            const uint32_t kx = (ks & 3) << 5;
            uint32_t ah[4][4], bh[8][2];
            #pragma unroll
            for (int mi = 0; mi < 4; mi++)
                ldsm4(ah[mi], asub + (abase[mi] ^ kx));
            #pragma unroll
            for (int p = 0; p < 4; p++) {
                uint32_t t4[4];
                ldsm4(t4, bsub + (bbase[p] ^ kx));
                bh[2 * p][0] = t4[0]; bh[2 * p][1] = t4[1];
                bh[2 * p + 1][0] = t4[2]; bh[2 * p + 1][1] = t4[3];
            }
            #pragma unroll
            for (int mi = 0; mi < 4; mi++)
                #pragma unroll
                for (int ni = 0; ni < 8; ni++)
                    mma_f16(acc[mi][ni], ah[mi], bh[ni]);
        }
        __syncthreads();
        if (c + 2 < NC) {
            uint32_t sb2 = sbase + (c & 1) * PG_STAGE;
            int k0 = (c + 2) * 128;
            load_rows64(sb2 + PG_A0, Ah, row0, k0,      E_DIM, 4);
            load_rows64(sb2 + PG_A1, Ah, row0, k0 + 64, E_DIM, 4);
            load_rows64(sb2 + PG_B0, Bh, n0,   k0,      E_DIM, 8);
            load_rows64(sb2 + PG_B1, Bh, n0,   k0 + 64, E_DIM, 8);
        }
        CP_COMMIT();
    }

    const int lg = lane >> 2;
    const int lc2 = (lane & 3) * 2;

    if (OUT_MODE == 2) {
        uint32_t* buf = reinterpret_cast<uint32_t*>(smdyn);
        const int P = 257;
        #pragma unroll
        for (int mi = 0; mi < 4; mi++) {
            #pragma unroll
            for (int half = 0; half < 2; half++) {
                int t = wm + mi * 16 + lg + half * 8;
                #pragma unroll
                for (int ni = 0; ni < 8; ni++) {
                    int j = wn + ni * 8 + lc2;
                    float v0 = acc[mi][ni][half * 2 + 0] + bias[n0 + j];
                    float v1 = acc[mi][ni][half * 2 + 1] + bias[n0 + j + 1];
                    buf[t * P + j]     = (uint32_t)__half_as_ushort(__float2half_rn(v0));
                    buf[t * P + j + 1] = (uint32_t)__half_as_ushort(__float2half_rn(v1));
                }
            }
        }
        __syncthreads();
        const int b = row0 >> 12;
        const int t0 = row0 & 4095;
        #pragma unroll 4
        for (int pass = 0; pass < 16; pass++) {
            int j = pass * 16 + (tid >> 4);
            int tq = (tid & 15) * 8;
            uint32_t hv[4];
            #pragma unroll
            for (int q = 0; q < 4; q++) {
                uint32_t w0 = buf[(tq + 2 * q) * P + j];
                uint32_t w1 = buf[(tq + 2 * q + 1) * P + j];
                hv[q] = (w0 & 0xFFFFu) | (w1 << 16);
            }
            size_t base = ((size_t)b * E_DIM + (n0 + j)) * T_DIM + t0 + tq;
            *reinterpret_cast<uint4*>(C1 + base) = make_uint4(hv[0], hv[1], hv[2], hv[3]);
        }
    } else {
        #pragma unroll
        for (int mi = 0; mi < 4; mi++) {
            #pragma unroll
            for (int half = 0; half < 2; half++) {
                int row = row0 + wm + mi * 16 + lg + half * 8;
                #pragma unroll
                for (int ni = 0; ni < 8; ni++) {
                    int col = n0 + wn + ni * 8 + lc2;
                    float v0 = acc[mi][ni][half * 2 + 0] + bias[col];
                    float v1 = acc[mi][ni][half * 2 + 1] + bias[col + 1];
                    if (OUT_MODE == 0) {
                        *reinterpret_cast<float2*>(Cf + (size_t)row * E_DIM + col) = make_float2(v0, v1);
                    } else {
                        *reinterpret_cast<uint32_t*>(C1 + (size_t)row * E_DIM + col) =
                            (uint32_t)__half_as_ushort(__float2half_rn(v0)) |
                            ((uint32_t)__half_as_ushort(__float2half_rn(v1)) << 16);
                    }
                }
            }
        }
    }
}

// ---------------- KV gemm: CTA 128x128 (e x d), warp 64x32, split-K ----------
#define KV_A 0
#define KV_B 16384
#define KV_STAGE 32768
#define KV_SMEM  (2 * KV_STAGE)

__global__ __launch_bounds__(256, 1) void k_kv_mma()
{
    const int split = blockIdx.x;
    const int bh = blockIdx.z;
    const int b = bh >> 4;
    const int h = bh & 15;
    const size_t hb = ((size_t)b * E_DIM + h * 128) * T_DIM;
    const f16* Ah = g_VTh + hb;   // rows e, K over t
    const f16* Bh = g_KTh + hb;   // rows d
    const int acol = split * (T_DIM / KVSPLIT);

    extern __shared__ __align__(1024) char smdyn[];
    const uint32_t sbase = smem_u32(smdyn);
    const int tid = threadIdx.x;
    const int wid = tid >> 5, lane = tid & 31;
    const int wm = (wid & 1) * 64;
    const int wn = (wid >> 1) * 32;

    uint32_t abase[4];
    #pragma unroll
    for (int mi = 0; mi < 4; mi++) {
        int r = wm + mi * 16 + (lane & 15);
        int hi = lane >> 4;
        abase[mi] = r * 128 + ((hi ^ (r & 7)) << 4);
    }
    uint32_t bbase[2];
    #pragma unroll
    for (int p = 0; p < 2; p++) {
        int g2 = lane >> 3;
        int r = wn + p * 16 + ((g2 >> 1) << 3) + (lane & 7);
        bbase[p] = r * 128 + (((g2 & 1) ^ (r & 7)) << 4);
    }

    float acc[4][4][4];
    #pragma unroll
    for (int mi = 0; mi < 4; mi++)
        #pragma unroll
        for (int ni = 0; ni < 4; ni++)
            #pragma unroll
            for (int q = 0; q < 4; q++) acc[mi][ni][q] = 0.0f;

    #pragma unroll
    for (int i = 0; i < 2; i++) {
        uint32_t sb = sbase + i * KV_STAGE;
        int k0 = acol + i * 64;
        load_rows64(sb + KV_A, Ah, 0, k0, T_DIM, 4);
        load_rows64(sb + KV_B, Bh, 0, k0, T_DIM, 4);
        CP_COMMIT();
    }

    const int NC = (T_DIM / KVSPLIT) / 64;   // 8
    for (int c = 0; c < NC; c++) {
        CP_WAIT1();
        __syncthreads();
        const uint32_t sb = sbase + (c & 1) * KV_STAGE;
        #pragma unroll
        for (int ks = 0; ks < 4; ks++) {
            const uint32_t kx = ks << 5;
            uint32_t ah[4][4], bh[4][2];
            #pragma unroll
            for (int mi = 0; mi < 4; mi++)
                ldsm4(ah[mi], sb + KV_A + (abase[mi] ^ kx));
            #pragma unroll
            for (int p = 0; p < 2; p++) {
                uint32_t t4[4];
                ldsm4(t4, sb + KV_B + (bbase[p] ^ kx));
                bh[2 * p][0] = t4[0]; bh[2 * p][1] = t4[1];
                bh[2 * p + 1][0] = t4[2]; bh[2 * p + 1][1] = t4[3];
            }
            #pragma unroll
            for (int mi = 0; mi < 4; mi++)
                #pragma unroll
                for (int ni = 0; ni < 4; ni++)
                    mma_f16(acc[mi][ni], ah[mi], bh[ni]);
        }
        __syncthreads();
        if (c + 2 < NC) {
            uint32_t sb2 = sbase + (c & 1) * KV_STAGE;
            int k0 = acol + (c + 2) * 64;
            load_rows64(sb2 + KV_A, Ah, 0, k0, T_DIM, 4);
            load_rows64(sb2 + KV_B, Bh, 0, k0, T_DIM, 4);
        }
        CP_COMMIT();
    }

    float* Cg = g_KVp + ((size_t)(split * 64 + bh) << 14);
    const int lg = lane >> 2;
    const int lc2 = (lane & 3) * 2;
    #pragma unroll
    for (int mi = 0; mi < 4; mi++)
        #pragma unroll
        for (int half = 0; half < 2; half++) {
            int row = wm + mi * 16 + lg + half * 8;   // e
            #pragma unroll
            for (int ni = 0; ni < 4; ni++) {
                int col = wn + ni * 8 + lc2;          // d
                *reinterpret_cast<float2*>(Cg + row * D_DIM + col) =
                    make_float2(acc[mi][ni][half * 2 + 0], acc[mi][ni][half * 2 + 1]);
            }
        }
}

// ---------------- attn GEMM: CTA 128x128, K=128 ------------------------------
#define AT_STAGE 16384
#define AT_SMEM  (3 * AT_STAGE)

__device__ __forceinline__ void load_tile128(uint32_t sdst, const f16* __restrict__ g,
                                             int row0, int col0, int ld) {
    const int t = threadIdx.x;
    #pragma unroll
    for (int i = 0; i < 2; i++) {
        int idx = t + i * 256;
        int r = idx >> 2, c = idx & 3;
        const f16* src = g + (size_t)(row0 + r) * ld + col0 + c * 8;
        uint32_t off = r * 64 + ((c ^ ((r >> 1) & 3)) << 4);
        cp_async16(sdst + off, src);
    }
}

__global__ __launch_bounds__(256) void k_gemm_attn()
{
    const float alpha = 0.08838834764831845f;   // 1/sqrt(128)
    const int h = blockIdx.z;
    const int row0 = blockIdx.y * 128;
    const int b = row0 >> 12;
    const int bh = (b << 4) + h;
    const f16* Ah = g_Qh;
    const f16* Bh = g_KVth + ((size_t)bh << 14);
    const int acol = h * 128;

    extern __shared__ __align__(1024) char smdyn[];
    const uint32_t sbase = smem_u32(smdyn);
    const int tid = threadIdx.x;
    const int wid = tid >> 5, lane = tid & 31;
    const int wm = (wid & 1) * 64;
    const int wn = (wid >> 1) * 32;

    uint32_t aoff[4][2];
    #pragma unroll
    for (int mi = 0; mi < 4; mi++) {
        int r = wm + mi * 16 + (lane & 15);
        #pragma unroll
        for (int ks = 0; ks < 2; ks++) {
            int kc = ks * 2 + (lane >> 4);
            aoff[mi][ks] = r * 64 + ((kc ^ ((r >> 1) & 3)) << 4);
        }
    }
    uint32_t boff[2][2];
    #pragma unroll
    for (int p = 0; p < 2; p++) {
        int g2 = lane >> 3;
        int r = wn + p * 16 + ((g2 >> 1) << 3) + (lane & 7);
        #pragma unroll
        for (int ks = 0; ks < 2; ks++) {
            int kc = ks * 2 + (g2 & 1);
            boff[p][ks] = r * 64 + ((kc ^ ((r >> 1) & 3)) << 4);
        }
    }

    float acc[4][4][4];
    #pragma unroll
    for (int mi = 0; mi < 4; mi++)
        #pragma unroll
        for (int ni = 0; ni < 4; ni++)
            #pragma unroll
            for (int q = 0; q < 4; q++) acc[mi][ni][q] = 0.0f;

    #pragma unroll
    for (int i = 0; i < 2; i++) {
        uint32_t sb = sbase + i * AT_STAGE;
        int k0 = i * 32;
        load_tile128(sb + 0,    Ah, row0, acol + k0, E_DIM);
        load_tile128(sb + 8192, Bh, 0, k0, D_DIM);
        CP_COMMIT();
    }

    for (int c = 0; c < 4; c++) {
        if (c + 2 < 4) {
            uint32_t sb = sbase + ((c + 2) % 3) * AT_STAGE;
            int k0 = (c + 2) * 32;
            load_tile128(sb + 0,    Ah, row0, acol + k0, E_DIM);
            load_tile128(sb + 8192, Bh, 0, k0, D_DIM);
        }
        CP_COMMIT();
        CP_WAIT2();
        __syncthreads();

        const uint32_t sb = sbase + (c % 3) * AT_STAGE;
        #pragma unroll
        for (int ks = 0; ks < 2; ks++) {
            uint32_t ah[4][4], bh[4][2];
            #pragma unroll
            for (int mi = 0; mi < 4; mi++)
                ldsm4(ah[mi], sb + aoff[mi][ks]);
            #pragma unroll
            for (int p = 0; p < 2; p++) {
                uint32_t t4[4];
                ldsm4(t4, sb + 8192 + boff[p][ks]);
                bh[2 * p][0] = t4[0]; bh[2 * p][1] = t4[1];
                bh[2 * p + 1][0] = t4[2]; bh[2 * p + 1][1] = t4[3];
            }
            #pragma unroll
            for (int mi = 0; mi < 4; mi++)
                #pragma unroll
                for (int ni = 0; ni < 4; ni++)
                    mma_f16(acc[mi][ni], ah[mi], bh[ni]);
        }
        __syncthreads();
    }

    const int lg = lane >> 2;
    const int lc2 = (lane & 3) * 2;
    #pragma unroll
    for (int mi = 0; mi < 4; mi++) {
        #pragma unroll
        for (int half = 0; half < 2; half++) {
            int row = row0 + wm + mi * 16 + lg + half * 8;
            #pragma unroll
            for (int ni = 0; ni < 4; ni++) {
                int col = h * 128 + wn + ni * 8 + lc2;
                float v0 = alpha * acc[mi][ni][half * 2 + 0];
                float v1 = alpha * acc[mi][ni][half * 2 + 1];
                *reinterpret_cast<uint32_t*>(g_ATh + (size_t)row * E_DIM + col) =
                    (uint32_t)__half_as_ushort(__float2half_rn(v0)) |
                    ((uint32_t)__half_as_ushort(__float2half_rn(v1)) << 16);
            }
        }
    }
}

// fp32 -> fp16
__global__ __launch_bounds__(256) void k_split(const float* __restrict__ in,
                                               f16* __restrict__ hp, int n)
{
    int i = (blockIdx.x * 256 + threadIdx.x) * 4;
    if (i >= n) return;
    float4 v = *reinterpret_cast<const float4*>(in + i);
    uint32_t hw[2];
    hw[0] = (uint32_t)__half_as_ushort(__float2half_rn(v.x)) |
            ((uint32_t)__half_as_ushort(__float2half_rn(v.y)) << 16);
    hw[1] = (uint32_t)__half_as_ushort(__float2half_rn(v.z)) |
            ((uint32_t)__half_as_ushort(__float2half_rn(v.w)) << 16);
    *reinterpret_cast<uint2*>(hp + i) = make_uint2(hw[0], hw[1]);
}

__global__ __launch_bounds__(256) void k_kvreduce()
{
    int idx = blockIdx.x * 256 + threadIdx.x;
    float sv = 0.0f;
    #pragma unroll
    for (int p = 0; p < KVSPLIT; p++) sv += g_KVp[((size_t)p << 20) + idx];
    g_KVth[idx] = __float2half_rn(sv);
}

// ---------------- launch -----------------------------------------------------
extern "C" void kernel_launch(void* const* d_in, const int* in_sizes, int n_in,
                              void* d_out, int out_size)
{
    const float* x  = (const float*)d_in[0];
    const float* Wq = (const float*)d_in[1];
    const float* bq = (const float*)d_in[2];
    const float* Wk = (const float*)d_in[3];
    const float* bk = (const float*)d_in[4];
    const float* Wv = (const float*)d_in[5];
    const float* bv = (const float*)d_in[6];
    const float* Wo = (const float*)d_in[7];
    const float* bo = (const float*)d_in[8];
    float* out = (float*)d_out;

    f16 *xh, *wh, *qh, *ath, *kth, *vth;
    cudaGetSymbolAddress((void**)&xh, g_xh);
    cudaGetSymbolAddress((void**)&wh, g_Wh);
    cudaGetSymbolAddress((void**)&qh, g_Qh);
    cudaGetSymbolAddress((void**)&ath, g_ATh);
    cudaGetSymbolAddress((void**)&kth, g_KTh);
    cudaGetSymbolAddress((void**)&vth, g_VTh);

    cudaFuncSetAttribute(k_gemm_proj<0>, cudaFuncAttributeMaxDynamicSharedMemorySize, PG_SMEM);
    cudaFuncSetAttribute(k_gemm_proj<1>, cudaFuncAttributeMaxDynamicSharedMemorySize, PG_SMEM);
    cudaFuncSetAttribute(k_gemm_proj<2>, cudaFuncAttributeMaxDynamicSharedMemorySize, PG_SMEM);
    cudaFuncSetAttribute(k_kv_mma,       cudaFuncAttributeMaxDynamicSharedMemorySize, KV_SMEM);
    cudaFuncSetAttribute(k_gemm_attn,    cudaFuncAttributeMaxDynamicSharedMemorySize, AT_SMEM);

    const size_t WSZ = (size_t)E_DIM * E_DIM;
    const int NX = BT_DIM * E_DIM;

    k_split<<<NX / 1024, 256>>>(x, xh, NX);
    k_split<<<(int)(WSZ / 1024), 256>>>(Wq, wh + 0 * WSZ, (int)WSZ);
    k_split<<<(int)(WSZ / 1024), 256>>>(Wk, wh + 1 * WSZ, (int)WSZ);
    k_split<<<(int)(WSZ / 1024), 256>>>(Wv, wh + 2 * WSZ, (int)WSZ);
    k_split<<<(int)(WSZ / 1024), 256>>>(Wo, wh + 3 * WSZ, (int)WSZ);

    dim3 gp(E_DIM / 256, BT_DIM / 128);  // (8, 128)

    k_gemm_proj<1><<<gp, 256, PG_SMEM>>>(xh, wh + 0 * WSZ, bq, nullptr, qh);
    k_gemm_proj<2><<<gp, 256, PG_SMEM>>>(xh, wh + 1 * WSZ, bk, nullptr, kth);
    k_gemm_proj<2><<<gp, 256, PG_SMEM>>>(xh, wh + 2 * WSZ, bv, nullptr, vth);

    k_kv_mma<<<dim3(KVSPLIT, 1, 64), 256, KV_SMEM>>>();
    k_kvreduce<<<(64 * D_DIM * D_DIM) / 256, 256>>>();

    k_gemm_attn<<<dim3(1, BT_DIM / 128, H_DIM), 256, AT_SMEM>>>();

    k_gemm_proj<0><<<gp, 256, PG_SMEM>>>(ath, wh + 3 * WSZ, bo, out, nullptr);
}

// round 9
// speedup vs baseline: 8.4942x; 1.0348x over previous
#include <cuda_runtime.h>
#include <cuda_fp16.h>
#include <cstdint>

#define B_DIM 4
#define T_DIM 4096
#define E_DIM 2048
#define H_DIM 16
#define D_DIM 128
#define BT_DIM 16384
#define KVSPLIT 8

typedef __half f16;

// ---------------- scratch (device globals; no allocations allowed) ----------
__device__ f16 g_xh[(size_t)BT_DIM * E_DIM];
__device__ f16 g_Wh[4][(size_t)E_DIM * E_DIM];
__device__ f16 g_Qh[(size_t)BT_DIM * E_DIM];
__device__ f16 g_Kh[(size_t)BT_DIM * E_DIM];   // row-major [b*T+t][e]
__device__ f16 g_Vh[(size_t)BT_DIM * E_DIM];
__device__ f16 g_ATh[(size_t)BT_DIM * E_DIM];
__device__ float g_KVp[(size_t)KVSPLIT * 64 * D_DIM * D_DIM];
__device__ f16 g_KVth[64 * D_DIM * D_DIM];

// ---------------- helpers ----------------------------------------------------
__device__ __forceinline__ uint32_t smem_u32(const void* p) {
    uint32_t a;
    asm("{ .reg .u64 t; cvta.to.shared.u64 t, %1; cvt.u32.u64 %0, t; }" : "=r"(a) : "l"(p));
    return a;
}
__device__ __forceinline__ void cp_async16(uint32_t sdst, const void* gsrc) {
    asm volatile("cp.async.cg.shared.global [%0], [%1], 16;" :: "r"(sdst), "l"(gsrc) : "memory");
}
#define CP_COMMIT() asm volatile("cp.async.commit_group;" ::: "memory")
#define CP_WAIT1()  asm volatile("cp.async.wait_group 1;" ::: "memory")
#define CP_WAIT2()  asm volatile("cp.async.wait_group 2;" ::: "memory")

__device__ __forceinline__ void ldsm4(uint32_t* r, uint32_t a) {
    asm volatile("ldmatrix.sync.aligned.m8n8.x4.shared.b16 {%0,%1,%2,%3}, [%4];"
                 : "=r"(r[0]), "=r"(r[1]), "=r"(r[2]), "=r"(r[3]) : "r"(a));
}
__device__ __forceinline__ void ldsm4t(uint32_t* r, uint32_t a) {
    asm volatile("ldmatrix.sync.aligned.m8n8.x4.trans.shared.b16 {%0,%1,%2,%3}, [%4];"
                 : "=r"(r[0]), "=r"(r[1]), "=r"(r[2]), "=r"(r[3]) : "r"(a));
}
__device__ __forceinline__ void mma_f16(float* c, const uint32_t* a, const uint32_t* b) {
    asm volatile(
        "mma.sync.aligned.m16n8k16.row.col.f32.f16.f16.f32 "
        "{%0,%1,%2,%3}, {%4,%5,%6,%7}, {%8,%9}, {%0,%1,%2,%3};"
        : "+f"(c[0]), "+f"(c[1]), "+f"(c[2]), "+f"(c[3])
        : "r"(a[0]), "r"(a[1]), "r"(a[2]), "r"(a[3]), "r"(b[0]), "r"(b[1]));
}

// tile loader: 128B rows (64 f16), 8x16B chunks, swizzle chunk c^(r&7)
__device__ __forceinline__ void load_rows64(uint32_t sdst, const f16* __restrict__ g,
                                            int row0, int col0, int ld, int iters) {
    const int t = threadIdx.x;
    #pragma unroll 8
    for (int i = 0; i < iters; i++) {
        int idx = t + i * 256;
        int r = idx >> 3, c = idx & 7;
        const f16* src = g + (size_t)(row0 + r) * ld + col0 + c * 8;
        cp_async16(sdst + r * 128 + ((c ^ (r & 7)) << 4), src);
    }
}

// ---------------- big GEMM core: CTA 128x256, warp 64x64, BK=128, 2 stages ---
#define PG_A0 0
#define PG_A1 16384
#define PG_B0 32768
#define PG_B1 65536
#define PG_STAGE 98304
#define PG_SMEM  (2 * PG_STAGE)

// out_f32: write fp32 to Cf, else f16 to C1. Both row-major [bt][e] (+bias).
__device__ __forceinline__ void gemm_128x256_core(
    const f16* __restrict__ Ah, const f16* __restrict__ Bh,
    const float* __restrict__ bias, bool out_f32,
    float* __restrict__ Cf, f16* __restrict__ C1)
{
    extern __shared__ __align__(1024) char smdyn[];
    const uint32_t sbase = smem_u32(smdyn);
    const int tid = threadIdx.x;
    const int wid = tid >> 5, lane = tid & 31;
    const int wm = (wid & 1) * 64;
    const int wn = (wid >> 1) * 64;
    const int row0 = blockIdx.y * 128;
    const int n0 = blockIdx.x * 256;

    uint32_t abase[4];
    #pragma unroll
    for (int mi = 0; mi < 4; mi++) {
        int r = wm + mi * 16 + (lane & 15);
        int hi = lane >> 4;
        abase[mi] = r * 128 + ((hi ^ (r & 7)) << 4);
    }
    uint32_t bbase[4];
    #pragma unroll
    for (int p = 0; p < 4; p++) {
        int g2 = lane >> 3;
        int r = wn + p * 16 + ((g2 >> 1) << 3) + (lane & 7);
        bbase[p] = r * 128 + (((g2 & 1) ^ (r & 7)) << 4);
    }

    float acc[4][8][4];
    #pragma unroll
    for (int mi = 0; mi < 4; mi++)
        #pragma unroll
        for (int ni = 0; ni < 8; ni++)
            #pragma unroll
            for (int q = 0; q < 4; q++) acc[mi][ni][q] = 0.0f;

    #pragma unroll
    for (int i = 0; i < 2; i++) {
        uint32_t sb = sbase + i * PG_STAGE;
        int k0 = i * 128;
        load_rows64(sb + PG_A0, Ah, row0, k0,      E_DIM, 4);
        load_rows64(sb + PG_A1, Ah, row0, k0 + 64, E_DIM, 4);
        load_rows64(sb + PG_B0, Bh, n0,   k0,      E_DIM, 8);
        load_rows64(sb + PG_B1, Bh, n0,   k0 + 64, E_DIM, 8);
        CP_COMMIT();
    }

    const int NC = E_DIM / 128;   // 16
    for (int c = 0; c < NC; c++) {
        CP_WAIT1();
        __syncthreads();
        const uint32_t sb = sbase + (c & 1) * PG_STAGE;
        #pragma unroll
        for (int ks = 0; ks < 8; ks++) {
            const uint32_t asub = sb + ((ks & 4) ? PG_A1 : PG_A0);
            const uint32_t bsub = sb + ((ks & 4) ? PG_B1 : PG_B0);
            const uint32_t kx = (ks & 3) << 5;
            uint32_t ah[4][4], bh[8][2];
            #pragma unroll
            for (int mi = 0; mi < 4; mi++)
                ldsm4(ah[mi], asub + (abase[mi] ^ kx));
            #pragma unroll
            for (int p = 0; p < 4; p++) {
                uint32_t t4[4];
                ldsm4(t4, bsub + (bbase[p] ^ kx));
                bh[2 * p][0] = t4[0]; bh[2 * p][1] = t4[1];
                bh[2 * p + 1][0] = t4[2]; bh[2 * p + 1][1] = t4[3];
            }
            #pragma unroll
            for (int mi = 0; mi < 4; mi++)
                #pragma unroll
                for (int ni = 0; ni < 8; ni++)
                    mma_f16(acc[mi][ni], ah[mi], bh[ni]);
        }
        __syncthreads();
        if (c + 2 < NC) {
            uint32_t sb2 = sbase + (c & 1) * PG_STAGE;
            int k0 = (c + 2) * 128;
            load_rows64(sb2 + PG_A0, Ah, row0, k0,      E_DIM, 4);
            load_rows64(sb2 + PG_A1, Ah, row0, k0 + 64, E_DIM, 4);
            load_rows64(sb2 + PG_B0, Bh, n0,   k0,      E_DIM, 8);
            load_rows64(sb2 + PG_B1, Bh, n0,   k0 + 64, E_DIM, 8);
        }
        CP_COMMIT();
    }

    const int lg = lane >> 2;
    const int lc2 = (lane & 3) * 2;
    #pragma unroll
    for (int mi = 0; mi < 4; mi++) {
        #pragma unroll
        for (int half = 0; half < 2; half++) {
            int row = row0 + wm + mi * 16 + lg + half * 8;
            #pragma unroll
            for (int ni = 0; ni < 8; ni++) {
                int col = n0 + wn + ni * 8 + lc2;
                float v0 = acc[mi][ni][half * 2 + 0] + bias[col];
                float v1 = acc[mi][ni][half * 2 + 1] + bias[col + 1];
                if (out_f32) {
                    *reinterpret_cast<float2*>(Cf + (size_t)row * E_DIM + col) = make_float2(v0, v1);
                } else {
                    *reinterpret_cast<uint32_t*>(C1 + (size_t)row * E_DIM + col) =
                        (uint32_t)__half_as_ushort(__float2half_rn(v0)) |
                        ((uint32_t)__half_as_ushort(__float2half_rn(v1)) << 16);
                }
            }
        }
    }
}

// fused Q/K/V projections: grid (8, 128, 3)
__global__ __launch_bounds__(256, 1) void k_qkv(
    const f16* __restrict__ xh, const f16* __restrict__ whBase,
    const float* __restrict__ bq, const float* __restrict__ bk, const float* __restrict__ bv)
{
    const int z = blockIdx.z;
    const size_t WSZ = (size_t)E_DIM * E_DIM;
    const f16* Bh = whBase + (size_t)z * WSZ;
    const float* bias = (z == 0) ? bq : (z == 1) ? bk : bv;
    f16* C1 = (z == 0) ? g_Qh : (z == 1) ? g_Kh : g_Vh;
    gemm_128x256_core(xh, Bh, bias, false, nullptr, C1);
}

// O projection: fp32 out
__global__ __launch_bounds__(256, 1) void k_oproj(
    const f16* __restrict__ wo, const float* __restrict__ bo, float* __restrict__ out)
{
    gemm_128x256_core(g_ATh, wo, bo, true, out, nullptr);
}

// ---------------- KV gemm: natural-layout operands via ldsm.trans ------------
// KV[bh][e][d] = sum_t V[b][t][h*128+e] * K[b][t][h*128+d], t in split range.
// smem tile: 64 t-rows x 256B (128 halves, 16 chunks), swizzle cc^(t&7).
#define KV_A 0
#define KV_B 16384
#define KV_STAGE 32768
#define KV_SMEM  (2 * KV_STAGE)

__device__ __forceinline__ void load_kv_tile(uint32_t sdst, const f16* __restrict__ g,
                                             int btrow0, int colh)
{
    const int t = threadIdx.x;
    #pragma unroll
    for (int i = 0; i < 4; i++) {
        int idx = t + i * 256;                 // 0..1023
        int r = idx >> 4, cc = idx & 15;       // t-row, chunk
        const f16* src = g + (size_t)(btrow0 + r) * E_DIM + colh + cc * 8;
        cp_async16(sdst + r * 256 + ((cc ^ (r & 7)) << 4), src);
    }
}

__global__ __launch_bounds__(256, 1) void k_kv_mma()
{
    const int split = blockIdx.x;
    const int bh = blockIdx.z;
    const int b = bh >> 4;
    const int h = bh & 15;
    const int colh = h * 128;
    const int bt_begin = b * T_DIM + split * (T_DIM / KVSPLIT);

    extern __shared__ __align__(1024) char smdyn[];
    const uint32_t sbase = smem_u32(smdyn);
    const int tid = threadIdx.x;
    const int wid = tid >> 5, lane = tid & 31;
    const int wm = (wid & 1) * 64;     // e offset
    const int wn = (wid >> 1) * 32;    // d offset
    const int q = lane >> 3;

    // A (V) trans frags: row r0a = ((q&2)<<2)+(lane&7), chunk = m0/8 + (q&1)
    uint32_t abase[4];
    #pragma unroll
    for (int mi = 0; mi < 4; mi++) {
        int r0 = ((q & 2) << 2) + (lane & 7);
        int cc = ((wm + mi * 16) >> 3) + (q & 1);
        abase[mi] = r0 * 256 + ((cc ^ (r0 & 7)) << 4);
    }
    // B (K) trans frags: row r0b = ((q&1)<<3)+(lane&7), chunk = n0/8 + (q>>1)
    uint32_t bbase[2];
    #pragma unroll
    for (int p = 0; p < 2; p++) {
        int r0 = ((q & 1) << 3) + (lane & 7);
        int cc = ((wn + p * 16) >> 3) + (q >> 1);
        bbase[p] = r0 * 256 + ((cc ^ (r0 & 7)) << 4);
    }

    float acc[4][4][4];
    #pragma unroll
    for (int mi = 0; mi < 4; mi++)
        #pragma unroll
        for (int ni = 0; ni < 4; ni++)
            #pragma unroll
            for (int qq = 0; qq < 4; qq++) acc[mi][ni][qq] = 0.0f;

    #pragma unroll
    for (int i = 0; i < 2; i++) {
        uint32_t sb = sbase + i * KV_STAGE;
        load_kv_tile(sb + KV_A, g_Vh, bt_begin + i * 64, colh);
        load_kv_tile(sb + KV_B, g_Kh, bt_begin + i * 64, colh);
        CP_COMMIT();
    }

    const int NC = (T_DIM / KVSPLIT) / 64;   // 8
    for (int c = 0; c < NC; c++) {
        CP_WAIT1();
        __syncthreads();
        const uint32_t sb = sbase + (c & 1) * KV_STAGE;
        #pragma unroll
        for (int ks = 0; ks < 4; ks++) {
            const uint32_t kofs = ks * 4096;   // 16 t-rows * 256B
            uint32_t ah[4][4], bh[4][2];
            #pragma unroll
            for (int mi = 0; mi < 4; mi++)
                ldsm4t(ah[mi], sb + KV_A + abase[mi] + kofs);
            #pragma unroll
            for (int p = 0; p < 2; p++) {
                uint32_t t4[4];
                ldsm4t(t4, sb + KV_B + bbase[p] + kofs);
                bh[2 * p][0] = t4[0]; bh[2 * p][1] = t4[1];
                bh[2 * p + 1][0] = t4[2]; bh[2 * p + 1][1] = t4[3];
            }
            #pragma unroll
            for (int mi = 0; mi < 4; mi++)
                #pragma unroll
                for (int ni = 0; ni < 4; ni++)
                    mma_f16(acc[mi][ni], ah[mi], bh[ni]);
        }
        __syncthreads();
        if (c + 2 < NC) {
            uint32_t sb2 = sbase + (c & 1) * KV_STAGE;
            load_kv_tile(sb2 + KV_A, g_Vh, bt_begin + (c + 2) * 64, colh);
            load_kv_tile(sb2 + KV_B, g_Kh, bt_begin + (c + 2) * 64, colh);
        }
        CP_COMMIT();
    }

    float* Cg = g_KVp + ((size_t)(split * 64 + bh) << 14);
    const int lg = lane >> 2;
    const int lc2 = (lane & 3) * 2;
    #pragma unroll
    for (int mi = 0; mi < 4; mi++)
        #pragma unroll
        for (int half = 0; half < 2; half++) {
            int row = wm + mi * 16 + lg + half * 8;   // e
            #pragma unroll
            for (int ni = 0; ni < 4; ni++) {
                int col = wn + ni * 8 + lc2;          // d
                *reinterpret_cast<float2*>(Cg + row * D_DIM + col) =
                    make_float2(acc[mi][ni][half * 2 + 0], acc[mi][ni][half * 2 + 1]);
            }
        }
}

// ---------------- attn GEMM: CTA 128x128, K=128 ------------------------------
#define AT_STAGE 16384
#define AT_SMEM  (3 * AT_STAGE)

__device__ __forceinline__ void load_tile128(uint32_t sdst, const f16* __restrict__ g,
                                             int row0, int col0, int ld) {
    const int t = threadIdx.x;
    #pragma unroll
    for (int i = 0; i < 2; i++) {
        int idx = t + i * 256;
        int r = idx >> 2, c = idx & 3;
        const f16* src = g + (size_t)(row0 + r) * ld + col0 + c * 8;
        uint32_t off = r * 64 + ((c ^ ((r >> 1) & 3)) << 4);
        cp_async16(sdst + off, src);
    }
}

__global__ __launch_bounds__(256) void k_gemm_attn()
{
    const float alpha = 0.08838834764831845f;   // 1/sqrt(128)
    const int h = blockIdx.z;
    const int row0 = blockIdx.y * 128;
    const int b = row0 >> 12;
    const int bh = (b << 4) + h;
    const f16* Ah = g_Qh;
    const f16* Bh = g_KVth + ((size_t)bh << 14);
    const int acol = h * 128;

    extern __shared__ __align__(1024) char smdyn[];
    const uint32_t sbase = smem_u32(smdyn);
    const int tid = threadIdx.x;
    const int wid = tid >> 5, lane = tid & 31;
    const int wm = (wid & 1) * 64;
    const int wn = (wid >> 1) * 32;

    uint32_t aoff[4][2];
    #pragma unroll
    for (int mi = 0; mi < 4; mi++) {
        int r = wm + mi * 16 + (lane & 15);
        #pragma unroll
        for (int ks = 0; ks < 2; ks++) {
            int kc = ks * 2 + (lane >> 4);
            aoff[mi][ks] = r * 64 + ((kc ^ ((r >> 1) & 3)) << 4);
        }
    }
    uint32_t boff[2][2];
    #pragma unroll
    for (int p = 0; p < 2; p++) {
        int g2 = lane >> 3;
        int r = wn + p * 16 + ((g2 >> 1) << 3) + (lane & 7);
        #pragma unroll
        for (int ks = 0; ks < 2; ks++) {
            int kc = ks * 2 + (g2 & 1);
            boff[p][ks] = r * 64 + ((kc ^ ((r >> 1) & 3)) << 4);
        }
    }

    float acc[4][4][4];
    #pragma unroll
    for (int mi = 0; mi < 4; mi++)
        #pragma unroll
        for (int ni = 0; ni < 4; ni++)
            #pragma unroll
            for (int qq = 0; qq < 4; qq++) acc[mi][ni][qq] = 0.0f;

    #pragma unroll
    for (int i = 0; i < 2; i++) {
        uint32_t sb = sbase + i * AT_STAGE;
        int k0 = i * 32;
        load_tile128(sb + 0,    Ah, row0, acol + k0, E_DIM);
        load_tile128(sb + 8192, Bh, 0, k0, D_DIM);
        CP_COMMIT();
    }

    for (int c = 0; c < 4; c++) {
        if (c + 2 < 4) {
            uint32_t sb = sbase + ((c + 2) % 3) * AT_STAGE;
            int k0 = (c + 2) * 32;
            load_tile128(sb + 0,    Ah, row0, acol + k0, E_DIM);
            load_tile128(sb + 8192, Bh, 0, k0, D_DIM);
        }
        CP_COMMIT();
        CP_WAIT2();
        __syncthreads();

        const uint32_t sb = sbase + (c % 3) * AT_STAGE;
        #pragma unroll
        for (int ks = 0; ks < 2; ks++) {
            uint32_t ah[4][4], bh[4][2];
            #pragma unroll
            for (int mi = 0; mi < 4; mi++)
                ldsm4(ah[mi], sb + aoff[mi][ks]);
            #pragma unroll
            for (int p = 0; p < 2; p++) {
                uint32_t t4[4];
                ldsm4(t4, sb + 8192 + boff[p][ks]);
                bh[2 * p][0] = t4[0]; bh[2 * p][1] = t4[1];
                bh[2 * p + 1][0] = t4[2]; bh[2 * p + 1][1] = t4[3];
            }
            #pragma unroll
            for (int mi = 0; mi < 4; mi++)
                #pragma unroll
                for (int ni = 0; ni < 4; ni++)
                    mma_f16(acc[mi][ni], ah[mi], bh[ni]);
        }
        __syncthreads();
    }

    const int lg = lane >> 2;
    const int lc2 = (lane & 3) * 2;
    #pragma unroll
    for (int mi = 0; mi < 4; mi++) {
        #pragma unroll
        for (int half = 0; half < 2; half++) {
            int row = row0 + wm + mi * 16 + lg + half * 8;
            #pragma unroll
            for (int ni = 0; ni < 4; ni++) {
                int col = h * 128 + wn + ni * 8 + lc2;
                float v0 = alpha * acc[mi][ni][half * 2 + 0];
                float v1 = alpha * acc[mi][ni][half * 2 + 1];
                *reinterpret_cast<uint32_t*>(g_ATh + (size_t)row * E_DIM + col) =
                    (uint32_t)__half_as_ushort(__float2half_rn(v0)) |
                    ((uint32_t)__half_as_ushort(__float2half_rn(v1)) << 16);
            }
        }
    }
}

// fused fp32 -> fp16 conversion: x then 4 weight matrices
__global__ __launch_bounds__(256) void k_split_all(
    const float* __restrict__ x,
    const float* __restrict__ Wq, const float* __restrict__ Wk,
    const float* __restrict__ Wv, const float* __restrict__ Wo,
    f16* __restrict__ xh, f16* __restrict__ whBase)
{
    const size_t WSZ4 = (size_t)E_DIM * E_DIM / 4;     // float4 count per W
    const size_t NX4  = (size_t)BT_DIM * E_DIM / 4;
    size_t i4 = (size_t)blockIdx.x * 256 + threadIdx.x;
    const float* src;
    f16* dst;
    if (i4 < NX4) {
        src = x; dst = xh;
    } else {
        size_t r = i4 - NX4;
        int w = (int)(r / WSZ4);
        i4 = r - (size_t)w * WSZ4;
        src = (w == 0) ? Wq : (w == 1) ? Wk : (w == 2) ? Wv : Wo;
        dst = whBase + (size_t)w * E_DIM * E_DIM;
    }
    float4 v = *reinterpret_cast<const float4*>(src + i4 * 4);
    uint32_t hw0 = (uint32_t)__half_as_ushort(__float2half_rn(v.x)) |
                   ((uint32_t)__half_as_ushort(__float2half_rn(v.y)) << 16);
    uint32_t hw1 = (uint32_t)__half_as_ushort(__float2half_rn(v.z)) |
                   ((uint32_t)__half_as_ushort(__float2half_rn(v.w)) << 16);
    *reinterpret_cast<uint2*>(dst + i4 * 4) = make_uint2(hw0, hw1);
}

__global__ __launch_bounds__(256) void k_kvreduce()
{
    int idx = blockIdx.x * 256 + threadIdx.x;
    float sv = 0.0f;
    #pragma unroll
    for (int p = 0; p < KVSPLIT; p++) sv += g_KVp[((size_t)p << 20) + idx];
    g_KVth[idx] = __float2half_rn(sv);
}

// ---------------- launch -----------------------------------------------------
extern "C" void kernel_launch(void* const* d_in, const int* in_sizes, int n_in,
                              void* d_out, int out_size)
{
    const float* x  = (const float*)d_in[0];
    const float* Wq = (const float*)d_in[1];
    const float* bq = (const float*)d_in[2];
    const float* Wk = (const float*)d_in[3];
    const float* bk = (const float*)d_in[4];
    const float* Wv = (const float*)d_in[5];
    const float* bv = (const float*)d_in[6];
    const float* Wo = (const float*)d_in[7];
    const float* bo = (const float*)d_in[8];
    float* out = (float*)d_out;

    f16 *xh, *wh;
    cudaGetSymbolAddress((void**)&xh, g_xh);
    cudaGetSymbolAddress((void**)&wh, g_Wh);

    cudaFuncSetAttribute(k_qkv,      cudaFuncAttributeMaxDynamicSharedMemorySize, PG_SMEM);
    cudaFuncSetAttribute(k_oproj,    cudaFuncAttributeMaxDynamicSharedMemorySize, PG_SMEM);
    cudaFuncSetAttribute(k_kv_mma,   cudaFuncAttributeMaxDynamicSharedMemorySize, KV_SMEM);
    cudaFuncSetAttribute(k_gemm_attn, cudaFuncAttributeMaxDynamicSharedMemorySize, AT_SMEM);

    const size_t WSZ = (size_t)E_DIM * E_DIM;
    const size_t total4 = ((size_t)BT_DIM * E_DIM + 4 * WSZ) / 4;   // float4 elements

    k_split_all<<<(int)(total4 / 256), 256>>>(x, Wq, Wk, Wv, Wo, xh, wh);

    k_qkv<<<dim3(E_DIM / 256, BT_DIM / 128, 3), 256, PG_SMEM>>>(xh, wh, bq, bk, bv);

    k_kv_mma<<<dim3(KVSPLIT, 1, 64), 256, KV_SMEM>>>();
    k_kvreduce<<<(64 * D_DIM * D_DIM) / 256, 256>>>();

    k_gemm_attn<<<dim3(1, BT_DIM / 128, H_DIM), 256, AT_SMEM>>>();

    k_oproj<<<dim3(E_DIM / 256, BT_DIM / 128), 256, PG_SMEM>>>(wh + 3 * WSZ, bo, out);
}

// round 10
// speedup vs baseline: 8.6302x; 1.0160x over previous
#include <cuda_runtime.h>
#include <cuda_fp16.h>
#include <cstdint>

#define B_DIM 4
#define T_DIM 4096
#define E_DIM 2048
#define H_DIM 16
#define D_DIM 128
#define BT_DIM 16384
#define KVSPLIT 8

typedef __half f16;

// ---------------- scratch (device globals; no allocations allowed) ----------
__device__ f16 g_xh[(size_t)BT_DIM * E_DIM];
__device__ f16 g_Wh[4][(size_t)E_DIM * E_DIM];
__device__ f16 g_Qh[(size_t)BT_DIM * E_DIM];
__device__ f16 g_Kh[(size_t)BT_DIM * E_DIM];   // row-major [b*T+t][e]
__device__ f16 g_Vh[(size_t)BT_DIM * E_DIM];
__device__ f16 g_PB[(size_t)B_DIM * E_DIM * E_DIM];  // per-batch merged KV*Wo^T
__device__ float g_KVp[(size_t)KVSPLIT * 64 * D_DIM * D_DIM];
__device__ f16 g_KVth[64 * D_DIM * D_DIM];           // [bh][d][e], alpha-folded

// ---------------- helpers ----------------------------------------------------
__device__ __forceinline__ uint32_t smem_u32(const void* p) {
    uint32_t a;
    asm("{ .reg .u64 t; cvta.to.shared.u64 t, %1; cvt.u32.u64 %0, t; }" : "=r"(a) : "l"(p));
    return a;
}
__device__ __forceinline__ void cp_async16(uint32_t sdst, const void* gsrc) {
    asm volatile("cp.async.cg.shared.global [%0], [%1], 16;" :: "r"(sdst), "l"(gsrc) : "memory");
}
#define CP_COMMIT() asm volatile("cp.async.commit_group;" ::: "memory")
#define CP_WAIT1()  asm volatile("cp.async.wait_group 1;" ::: "memory")
#define CP_WAIT2()  asm volatile("cp.async.wait_group 2;" ::: "memory")

__device__ __forceinline__ void ldsm4(uint32_t* r, uint32_t a) {
    asm volatile("ldmatrix.sync.aligned.m8n8.x4.shared.b16 {%0,%1,%2,%3}, [%4];"
                 : "=r"(r[0]), "=r"(r[1]), "=r"(r[2]), "=r"(r[3]) : "r"(a));
}
__device__ __forceinline__ void ldsm4t(uint32_t* r, uint32_t a) {
    asm volatile("ldmatrix.sync.aligned.m8n8.x4.trans.shared.b16 {%0,%1,%2,%3}, [%4];"
                 : "=r"(r[0]), "=r"(r[1]), "=r"(r[2]), "=r"(r[3]) : "r"(a));
}
__device__ __forceinline__ void mma_f16(float* c, const uint32_t* a, const uint32_t* b) {
    asm volatile(
        "mma.sync.aligned.m16n8k16.row.col.f32.f16.f16.f32 "
        "{%0,%1,%2,%3}, {%4,%5,%6,%7}, {%8,%9}, {%0,%1,%2,%3};"
        : "+f"(c[0]), "+f"(c[1]), "+f"(c[2]), "+f"(c[3])
        : "r"(a[0]), "r"(a[1]), "r"(a[2]), "r"(a[3]), "r"(b[0]), "r"(b[1]));
}

// tile loader: 128B rows (64 f16), 8x16B chunks, swizzle chunk c^(r&7)
__device__ __forceinline__ void load_rows64(uint32_t sdst, const f16* __restrict__ g,
                                            int row0, int col0, int ld, int iters) {
    const int t = threadIdx.x;
    #pragma unroll 8
    for (int i = 0; i < iters; i++) {
        int idx = t + i * 256;
        int r = idx >> 3, c = idx & 7;
        const f16* src = g + (size_t)(row0 + r) * ld + col0 + c * 8;
        cp_async16(sdst + r * 128 + ((c ^ (r & 7)) << 4), src);
    }
}

// ---------------- big GEMM core: CTA 128x256, warp 64x64, BK=128, 2 stages ---
#define PG_A0 0
#define PG_A1 16384
#define PG_B0 32768
#define PG_B1 65536
#define PG_STAGE 98304
#define PG_SMEM  (2 * PG_STAGE)

__device__ __forceinline__ void gemm_128x256_core(
    const f16* __restrict__ Ah, const f16* __restrict__ Bh,
    const float* __restrict__ bias, bool out_f32,
    float* __restrict__ Cf, f16* __restrict__ C1)
{
    extern __shared__ __align__(1024) char smdyn[];
    const uint32_t sbase = smem_u32(smdyn);
    const int tid = threadIdx.x;
    const int wid = tid >> 5, lane = tid & 31;
    const int wm = (wid & 1) * 64;
    const int wn = (wid >> 1) * 64;
    const int row0 = blockIdx.y * 128;
    const int n0 = blockIdx.x * 256;

    uint32_t abase[4];
    #pragma unroll
    for (int mi = 0; mi < 4; mi++) {
        int r = wm + mi * 16 + (lane & 15);
        int hi = lane >> 4;
        abase[mi] = r * 128 + ((hi ^ (r & 7)) << 4);
    }
    uint32_t bbase[4];
    #pragma unroll
    for (int p = 0; p < 4; p++) {
        int g2 = lane >> 3;
        int r = wn + p * 16 + ((g2 >> 1) << 3) + (lane & 7);
        bbase[p] = r * 128 + (((g2 & 1) ^ (r & 7)) << 4);
    }

    float acc[4][8][4];
    #pragma unroll
    for (int mi = 0; mi < 4; mi++)
        #pragma unroll
        for (int ni = 0; ni < 8; ni++)
            #pragma unroll
            for (int q = 0; q < 4; q++) acc[mi][ni][q] = 0.0f;

    #pragma unroll
    for (int i = 0; i < 2; i++) {
        uint32_t sb = sbase + i * PG_STAGE;
        int k0 = i * 128;
        load_rows64(sb + PG_A0, Ah, row0, k0,      E_DIM, 4);
        load_rows64(sb + PG_A1, Ah, row0, k0 + 64, E_DIM, 4);
        load_rows64(sb + PG_B0, Bh, n0,   k0,      E_DIM, 8);
        load_rows64(sb + PG_B1, Bh, n0,   k0 + 64, E_DIM, 8);
        CP_COMMIT();
    }

    const int NC = E_DIM / 128;   // 16
    for (int c = 0; c < NC; c++) {
        CP_WAIT1();
        __syncthreads();
        const uint32_t sb = sbase + (c & 1) * PG_STAGE;
        #pragma unroll
        for (int ks = 0; ks < 8; ks++) {
            const uint32_t asub = sb + ((ks & 4) ? PG_A1 : PG_A0);
            const uint32_t bsub = sb + ((ks & 4) ? PG_B1 : PG_B0);
            const uint32_t kx = (ks & 3) << 5;
            uint32_t ah[4][4], bh[8][2];
            #pragma unroll
            for (int mi = 0; mi < 4; mi++)
                ldsm4(ah[mi], asub + (abase[mi] ^ kx));
            #pragma unroll
            for (int p = 0; p < 4; p++) {
                uint32_t t4[4];
                ldsm4(t4, bsub + (bbase[p] ^ kx));
                bh[2 * p][0] = t4[0]; bh[2 * p][1] = t4[1];
                bh[2 * p + 1][0] = t4[2]; bh[2 * p + 1][1] = t4[3];
            }
            #pragma unroll
            for (int mi = 0; mi < 4; mi++)
                #pragma unroll
                for (int ni = 0; ni < 8; ni++)
                    mma_f16(acc[mi][ni], ah[mi], bh[ni]);
        }
        __syncthreads();
        if (c + 2 < NC) {
            uint32_t sb2 = sbase + (c & 1) * PG_STAGE;
            int k0 = (c + 2) * 128;
            load_rows64(sb2 + PG_A0, Ah, row0, k0,      E_DIM, 4);
            load_rows64(sb2 + PG_A1, Ah, row0, k0 + 64, E_DIM, 4);
            load_rows64(sb2 + PG_B0, Bh, n0,   k0,      E_DIM, 8);
            load_rows64(sb2 + PG_B1, Bh, n0,   k0 + 64, E_DIM, 8);
        }
        CP_COMMIT();
    }

    const int lg = lane >> 2;
    const int lc2 = (lane & 3) * 2;
    #pragma unroll
    for (int mi = 0; mi < 4; mi++) {
        #pragma unroll
        for (int half = 0; half < 2; half++) {
            int row = row0 + wm + mi * 16 + lg + half * 8;
            #pragma unroll
            for (int ni = 0; ni < 8; ni++) {
                int col = n0 + wn + ni * 8 + lc2;
                float v0 = acc[mi][ni][half * 2 + 0] + bias[col];
                float v1 = acc[mi][ni][half * 2 + 1] + bias[col + 1];
                if (out_f32) {
                    *reinterpret_cast<float2*>(Cf + (size_t)row * E_DIM + col) = make_float2(v0, v1);
                } else {
                    *reinterpret_cast<uint32_t*>(C1 + (size_t)row * E_DIM + col) =
                        (uint32_t)__half_as_ushort(__float2half_rn(v0)) |
                        ((uint32_t)__half_as_ushort(__float2half_rn(v1)) << 16);
                }
            }
        }
    }
}

// fused Q/K/V projections: grid (8, 128, 3)
__global__ __launch_bounds__(256, 1) void k_qkv(
    const f16* __restrict__ xh, const f16* __restrict__ whBase,
    const float* __restrict__ bq, const float* __restrict__ bk, const float* __restrict__ bv)
{
    const int z = blockIdx.z;
    const size_t WSZ = (size_t)E_DIM * E_DIM;
    const f16* Bh = whBase + (size_t)z * WSZ;
    const float* bias = (z == 0) ? bq : (z == 1) ? bk : bv;
    f16* C1 = (z == 0) ? g_Qh : (z == 1) ? g_Kh : g_Vh;
    gemm_128x256_core(xh, Bh, bias, false, nullptr, C1);
}

// final output: OUT = Q @ PB[b] + bo   (grid (8, 128))
__global__ __launch_bounds__(256, 1) void k_out(
    const float* __restrict__ bo, float* __restrict__ out)
{
    const int b = blockIdx.y >> 5;   // row0 / 4096
    gemm_128x256_core(g_Qh, g_PB + (size_t)b * E_DIM * E_DIM, bo, true, out, nullptr);
}

// ---------------- KV gemm: natural-layout operands via ldsm.trans ------------
// KVth[bh][d][e] (pre-reduce partials): Σ_t K[b][t][h*128+d] * V[b][t][h*128+e]
#define KV_A 0
#define KV_B 16384
#define KV_STAGE 32768
#define KV_SMEM  (2 * KV_STAGE)

__device__ __forceinline__ void load_kv_tile(uint32_t sdst, const f16* __restrict__ g,
                                             int btrow0, int colh)
{
    const int t = threadIdx.x;
    #pragma unroll
    for (int i = 0; i < 4; i++) {
        int idx = t + i * 256;                 // 0..1023
        int r = idx >> 4, cc = idx & 15;       // t-row, chunk
        const f16* src = g + (size_t)(btrow0 + r) * E_DIM + colh + cc * 8;
        cp_async16(sdst + r * 256 + ((cc ^ (r & 7)) << 4), src);
    }
}

__global__ __launch_bounds__(256, 1) void k_kv_mma()
{
    const int split = blockIdx.x;
    const int bh = blockIdx.z;
    const int b = bh >> 4;
    const int h = bh & 15;
    const int colh = h * 128;
    const int bt_begin = b * T_DIM + split * (T_DIM / KVSPLIT);

    extern __shared__ __align__(1024) char smdyn[];
    const uint32_t sbase = smem_u32(smdyn);
    const int tid = threadIdx.x;
    const int wid = tid >> 5, lane = tid & 31;
    const int wm = (wid & 1) * 64;     // d offset (A = K)
    const int wn = (wid >> 1) * 32;    // e offset (B = V)
    const int q = lane >> 3;

    uint32_t abase[4];
    #pragma unroll
    for (int mi = 0; mi < 4; mi++) {
        int r0 = ((q & 2) << 2) + (lane & 7);
        int cc = ((wm + mi * 16) >> 3) + (q & 1);
        abase[mi] = r0 * 256 + ((cc ^ (r0 & 7)) << 4);
    }
    uint32_t bbase[2];
    #pragma unroll
    for (int p = 0; p < 2; p++) {
        int r0 = ((q & 1) << 3) + (lane & 7);
        int cc = ((wn + p * 16) >> 3) + (q >> 1);
        bbase[p] = r0 * 256 + ((cc ^ (r0 & 7)) << 4);
    }

    float acc[4][4][4];
    #pragma unroll
    for (int mi = 0; mi < 4; mi++)
        #pragma unroll
        for (int ni = 0; ni < 4; ni++)
            #pragma unroll
            for (int qq = 0; qq < 4; qq++) acc[mi][ni][qq] = 0.0f;

    #pragma unroll
    for (int i = 0; i < 2; i++) {
        uint32_t sb = sbase + i * KV_STAGE;
        load_kv_tile(sb + KV_A, g_Kh, bt_begin + i * 64, colh);
        load_kv_tile(sb + KV_B, g_Vh, bt_begin + i * 64, colh);
        CP_COMMIT();
    }

    const int NC = (T_DIM / KVSPLIT) / 64;   // 8
    for (int c = 0; c < NC; c++) {
        CP_WAIT1();
        __syncthreads();
        const uint32_t sb = sbase + (c & 1) * KV_STAGE;
        #pragma unroll
        for (int ks = 0; ks < 4; ks++) {
            const uint32_t kofs = ks * 4096;
            uint32_t ah[4][4], bh[4][2];
            #pragma unroll
            for (int mi = 0; mi < 4; mi++)
                ldsm4t(ah[mi], sb + KV_A + abase[mi] + kofs);
            #pragma unroll
            for (int p = 0; p < 2; p++) {
                uint32_t t4[4];
                ldsm4t(t4, sb + KV_B + bbase[p] + kofs);
                bh[2 * p][0] = t4[0]; bh[2 * p][1] = t4[1];
                bh[2 * p + 1][0] = t4[2]; bh[2 * p + 1][1] = t4[3];
            }
            #pragma unroll
            for (int mi = 0; mi < 4; mi++)
                #pragma unroll
                for (int ni = 0; ni < 4; ni++)
                    mma_f16(acc[mi][ni], ah[mi], bh[ni]);
        }
        __syncthreads();
        if (c + 2 < NC) {
            uint32_t sb2 = sbase + (c & 1) * KV_STAGE;
            load_kv_tile(sb2 + KV_A, g_Kh, bt_begin + (c + 2) * 64, colh);
            load_kv_tile(sb2 + KV_B, g_Vh, bt_begin + (c + 2) * 64, colh);
        }
        CP_COMMIT();
    }

    float* Cg = g_KVp + ((size_t)(split * 64 + bh) << 14);
    const int lg = lane >> 2;
    const int lc2 = (lane & 3) * 2;
    #pragma unroll
    for (int mi = 0; mi < 4; mi++)
        #pragma unroll
        for (int half = 0; half < 2; half++) {
            int row = wm + mi * 16 + lg + half * 8;   // d
            #pragma unroll
            for (int ni = 0; ni < 4; ni++) {
                int col = wn + ni * 8 + lc2;          // e
                *reinterpret_cast<float2*>(Cg + row * D_DIM + col) =
                    make_float2(acc[mi][ni][half * 2 + 0], acc[mi][ni][half * 2 + 1]);
            }
        }
}

// reduce partials -> f16 [bh][d][e], with alpha = 1/sqrt(128) folded in
__global__ __launch_bounds__(256) void k_kvreduce()
{
    const float alpha = 0.08838834764831845f;
    int idx = blockIdx.x * 256 + threadIdx.x;
    float sv = 0.0f;
    #pragma unroll
    for (int p = 0; p < KVSPLIT; p++) sv += g_KVp[((size_t)p << 20) + idx];
    g_KVth[idx] = __float2half_rn(alpha * sv);
}

// ---------------- PB build: PB[b][n][h*128+d] = sum_e Wo[n,h*128+e]*KVth[bh][d][e]
// CTA 128(n) x 128(d), K=128(e). grid (1, 16, 64). Clone of old attn kernel.
#define AT_STAGE 16384
#define AT_SMEM  (3 * AT_STAGE)

__device__ __forceinline__ void load_tile128(uint32_t sdst, const f16* __restrict__ g,
                                             int row0, int col0, int ld) {
    const int t = threadIdx.x;
    #pragma unroll
    for (int i = 0; i < 2; i++) {
        int idx = t + i * 256;
        int r = idx >> 2, c = idx & 3;
        const f16* src = g + (size_t)(row0 + r) * ld + col0 + c * 8;
        uint32_t off = r * 64 + ((c ^ ((r >> 1) & 3)) << 4);
        cp_async16(sdst + off, src);
    }
}

__global__ __launch_bounds__(256) void k_pb(const f16* __restrict__ wo)
{
    const int bh = blockIdx.z;
    const int b = bh >> 4;
    const int h = bh & 15;
    const int row0 = blockIdx.y * 128;          // Wo n-row block (0..15)
    const f16* Ah = wo;                         // [n][e'] ld E_DIM, cols h*128..
    const f16* Bh = g_KVth + ((size_t)bh << 14); // [d][e] ld 128
    const int acol = h * 128;
    f16* PBb = g_PB + (size_t)b * E_DIM * E_DIM;

    extern __shared__ __align__(1024) char smdyn[];
    const uint32_t sbase = smem_u32(smdyn);
    const int tid = threadIdx.x;
    const int wid = tid >> 5, lane = tid & 31;
    const int wm = (wid & 1) * 64;
    const int wn = (wid >> 1) * 32;

    uint32_t aoff[4][2];
    #pragma unroll
    for (int mi = 0; mi < 4; mi++) {
        int r = wm + mi * 16 + (lane & 15);
        #pragma unroll
        for (int ks = 0; ks < 2; ks++) {
            int kc = ks * 2 + (lane >> 4);
            aoff[mi][ks] = r * 64 + ((kc ^ ((r >> 1) & 3)) << 4);
        }
    }
    uint32_t boff[2][2];
    #pragma unroll
    for (int p = 0; p < 2; p++) {
        int g2 = lane >> 3;
        int r = wn + p * 16 + ((g2 >> 1) << 3) + (lane & 7);
        #pragma unroll
        for (int ks = 0; ks < 2; ks++) {
            int kc = ks * 2 + (g2 & 1);
            boff[p][ks] = r * 64 + ((kc ^ ((r >> 1) & 3)) << 4);
        }
    }

    float acc[4][4][4];
    #pragma unroll
    for (int mi = 0; mi < 4; mi++)
        #pragma unroll
        for (int ni = 0; ni < 4; ni++)
            #pragma unroll
            for (int qq = 0; qq < 4; qq++) acc[mi][ni][qq] = 0.0f;

    #pragma unroll
    for (int i = 0; i < 2; i++) {
        uint32_t sb = sbase + i * AT_STAGE;
        int k0 = i * 32;
        load_tile128(sb + 0,    Ah, row0, acol + k0, E_DIM);
        load_tile128(sb + 8192, Bh, 0, k0, D_DIM);
        CP_COMMIT();
    }

    for (int c = 0; c < 4; c++) {
        if (c + 2 < 4) {
            uint32_t sb = sbase + ((c + 2) % 3) * AT_STAGE;
            int k0 = (c + 2) * 32;
            load_tile128(sb + 0,    Ah, row0, acol + k0, E_DIM);
            load_tile128(sb + 8192, Bh, 0, k0, D_DIM);
        }
        CP_COMMIT();
        CP_WAIT2();
        __syncthreads();

        const uint32_t sb = sbase + (c % 3) * AT_STAGE;
        #pragma unroll
        for (int ks = 0; ks < 2; ks++) {
            uint32_t ah[4][4], bh[4][2];
            #pragma unroll
            for (int mi = 0; mi < 4; mi++)
                ldsm4(ah[mi], sb + aoff[mi][ks]);
            #pragma unroll
            for (int p = 0; p < 2; p++) {
                uint32_t t4[4];
                ldsm4(t4, sb + 8192 + boff[p][ks]);
                bh[2 * p][0] = t4[0]; bh[2 * p][1] = t4[1];
                bh[2 * p + 1][0] = t4[2]; bh[2 * p + 1][1] = t4[3];
            }
            #pragma unroll
            for (int mi = 0; mi < 4; mi++)
                #pragma unroll
                for (int ni = 0; ni < 4; ni++)
                    mma_f16(acc[mi][ni], ah[mi], bh[ni]);
        }
        __syncthreads();
    }

    const int lg = lane >> 2;
    const int lc2 = (lane & 3) * 2;
    #pragma unroll
    for (int mi = 0; mi < 4; mi++) {
        #pragma unroll
        for (int half = 0; half < 2; half++) {
            int row = row0 + wm + mi * 16 + lg + half * 8;    // n
            #pragma unroll
            for (int ni = 0; ni < 4; ni++) {
                int col = h * 128 + wn + ni * 8 + lc2;        // k = h*128+d
                *reinterpret_cast<uint32_t*>(PBb + (size_t)row * E_DIM + col) =
                    (uint32_t)__half_as_ushort(__float2half_rn(acc[mi][ni][half * 2 + 0])) |
                    ((uint32_t)__half_as_ushort(__float2half_rn(acc[mi][ni][half * 2 + 1])) << 16);
            }
        }
    }
}

// fused fp32 -> fp16 conversion: x then 4 weight matrices
__global__ __launch_bounds__(256) void k_split_all(
    const float* __restrict__ x,
    const float* __restrict__ Wq, const float* __restrict__ Wk,
    const float* __restrict__ Wv, const float* __restrict__ Wo,
    f16* __restrict__ xh, f16* __restrict__ whBase)
{
    const size_t WSZ4 = (size_t)E_DIM * E_DIM / 4;
    const size_t NX4  = (size_t)BT_DIM * E_DIM / 4;
    size_t i4 = (size_t)blockIdx.x * 256 + threadIdx.x;
    const float* src;
    f16* dst;
    if (i4 < NX4) {
        src = x; dst = xh;
    } else {
        size_t r = i4 - NX4;
        int w = (int)(r / WSZ4);
        i4 = r - (size_t)w * WSZ4;
        src = (w == 0) ? Wq : (w == 1) ? Wk : (w == 2) ? Wv : Wo;
        dst = whBase + (size_t)w * E_DIM * E_DIM;
    }
    float4 v = *reinterpret_cast<const float4*>(src + i4 * 4);
    uint32_t hw0 = (uint32_t)__half_as_ushort(__float2half_rn(v.x)) |
                   ((uint32_t)__half_as_ushort(__float2half_rn(v.y)) << 16);
    uint32_t hw1 = (uint32_t)__half_as_ushort(__float2half_rn(v.z)) |
                   ((uint32_t)__half_as_ushort(__float2half_rn(v.w)) << 16);
    *reinterpret_cast<uint2*>(dst + i4 * 4) = make_uint2(hw0, hw1);
}

// ---------------- launch -----------------------------------------------------
extern "C" void kernel_launch(void* const* d_in, const int* in_sizes, int n_in,
                              void* d_out, int out_size)
{
    const float* x  = (const float*)d_in[0];
    const float* Wq = (const float*)d_in[1];
    const float* bq = (const float*)d_in[2];
    const float* Wk = (const float*)d_in[3];
    const float* bk = (const float*)d_in[4];
    const float* Wv = (const float*)d_in[5];
    const float* bv = (const float*)d_in[6];
    const float* Wo = (const float*)d_in[7];
    const float* bo = (const float*)d_in[8];
    float* out = (float*)d_out;

    f16 *xh, *wh;
    cudaGetSymbolAddress((void**)&xh, g_xh);
    cudaGetSymbolAddress((void**)&wh, g_Wh);

    cudaFuncSetAttribute(k_qkv,    cudaFuncAttributeMaxDynamicSharedMemorySize, PG_SMEM);
    cudaFuncSetAttribute(k_out,    cudaFuncAttributeMaxDynamicSharedMemorySize, PG_SMEM);
    cudaFuncSetAttribute(k_kv_mma, cudaFuncAttributeMaxDynamicSharedMemorySize, KV_SMEM);
    cudaFuncSetAttribute(k_pb,     cudaFuncAttributeMaxDynamicSharedMemorySize, AT_SMEM);

    const size_t WSZ = (size_t)E_DIM * E_DIM;
    const size_t total4 = ((size_t)BT_DIM * E_DIM + 4 * WSZ) / 4;

    k_split_all<<<(int)(total4 / 256), 256>>>(x, Wq, Wk, Wv, Wo, xh, wh);

    k_qkv<<<dim3(E_DIM / 256, BT_DIM / 128, 3), 256, PG_SMEM>>>(xh, wh, bq, bk, bv);

    k_kv_mma<<<dim3(KVSPLIT, 1, 64), 256, KV_SMEM>>>();
    k_kvreduce<<<(64 * D_DIM * D_DIM) / 256, 256>>>();

    k_pb<<<dim3(1, E_DIM / 128, 64), 256, AT_SMEM>>>(wh + 3 * WSZ);

    k_out<<<dim3(E_DIM / 256, BT_DIM / 128), 256, PG_SMEM>>>(bo, out);
}

// round 11
// speedup vs baseline: 9.4492x; 1.0949x over previous
#include <cuda_runtime.h>
#include <cuda_fp16.h>
#include <cstdint>

#define B_DIM 4
#define T_DIM 4096
#define E_DIM 2048
#define H_DIM 16
#define D_DIM 128
#define BT_DIM 16384
#define KVSPLIT 8

typedef __half f16;

// ---------------- scratch (device globals; no allocations allowed) ----------
__device__ f16 g_xh[(size_t)BT_DIM * E_DIM];
__device__ f16 g_Wh[4][(size_t)E_DIM * E_DIM];
__device__ f16 g_Kh[(size_t)BT_DIM * E_DIM];
__device__ f16 g_Vh[(size_t)BT_DIM * E_DIM];
__device__ f16 g_PB[(size_t)B_DIM * E_DIM * E_DIM];  // per-batch KV*Wo^T  [n][k]
__device__ f16 g_M[(size_t)B_DIM * E_DIM * E_DIM];   // Mt[b][n][j] = (Wq^T PB)^T
__device__ float g_fbias[B_DIM * E_DIM];             // bq@PB^T + bo per batch
__device__ float g_KVp[(size_t)KVSPLIT * 64 * D_DIM * D_DIM];
__device__ f16 g_KVth[64 * D_DIM * D_DIM];           // [bh][d][e], alpha-folded

// ---------------- helpers ----------------------------------------------------
__device__ __forceinline__ uint32_t smem_u32(const void* p) {
    uint32_t a;
    asm("{ .reg .u64 t; cvta.to.shared.u64 t, %1; cvt.u32.u64 %0, t; }" : "=r"(a) : "l"(p));
    return a;
}
__device__ __forceinline__ void cp_async16(uint32_t sdst, const void* gsrc) {
    asm volatile("cp.async.cg.shared.global [%0], [%1], 16;" :: "r"(sdst), "l"(gsrc) : "memory");
}
#define CP_COMMIT() asm volatile("cp.async.commit_group;" ::: "memory")
#define CP_WAIT1()  asm volatile("cp.async.wait_group 1;" ::: "memory")
#define CP_WAIT2()  asm volatile("cp.async.wait_group 2;" ::: "memory")

__device__ __forceinline__ void ldsm4(uint32_t* r, uint32_t a) {
    asm volatile("ldmatrix.sync.aligned.m8n8.x4.shared.b16 {%0,%1,%2,%3}, [%4];"
                 : "=r"(r[0]), "=r"(r[1]), "=r"(r[2]), "=r"(r[3]) : "r"(a));
}
__device__ __forceinline__ void ldsm4t(uint32_t* r, uint32_t a) {
    asm volatile("ldmatrix.sync.aligned.m8n8.x4.trans.shared.b16 {%0,%1,%2,%3}, [%4];"
                 : "=r"(r[0]), "=r"(r[1]), "=r"(r[2]), "=r"(r[3]) : "r"(a));
}
__device__ __forceinline__ void mma_f16(float* c, const uint32_t* a, const uint32_t* b) {
    asm volatile(
        "mma.sync.aligned.m16n8k16.row.col.f32.f16.f16.f32 "
        "{%0,%1,%2,%3}, {%4,%5,%6,%7}, {%8,%9}, {%0,%1,%2,%3};"
        : "+f"(c[0]), "+f"(c[1]), "+f"(c[2]), "+f"(c[3])
        : "r"(a[0]), "r"(a[1]), "r"(a[2]), "r"(a[3]), "r"(b[0]), "r"(b[1]));
}

// tile loader: 128B rows (64 f16), 8x16B chunks, swizzle chunk c^(r&7)
__device__ __forceinline__ void load_rows64(uint32_t sdst, const f16* __restrict__ g,
                                            int row0, int col0, int ld, int iters) {
    const int t = threadIdx.x;
    #pragma unroll 8
    for (int i = 0; i < iters; i++) {
        int idx = t + i * 256;
        int r = idx >> 3, c = idx & 7;
        const f16* src = g + (size_t)(row0 + r) * ld + col0 + c * 8;
        cp_async16(sdst + r * 128 + ((c ^ (r & 7)) << 4), src);
    }
}

// trans tile loader: 64 k-rows x 512B (256 f16 cols), swizzle cc^(r&7)
__device__ __forceinline__ void load_trans_tile(uint32_t sdst, const f16* __restrict__ g,
                                                int k0, int j0, int ld) {
    const int t = threadIdx.x;
    #pragma unroll
    for (int i = 0; i < 8; i++) {
        int idx = t + i * 256;                 // 0..2047
        int r = idx >> 5, cc = idx & 31;
        const f16* src = g + (size_t)(k0 + r) * ld + j0 + cc * 8;
        cp_async16(sdst + r * 512 + ((cc ^ (r & 7)) << 4), src);
    }
}

// ---------------- big GEMM core: CTA 128x256, warp 64x64, BK=128, 2 stages ---
#define PG_A0 0
#define PG_A1 16384
#define PG_B0 32768
#define PG_B1 65536
#define PG_STAGE 98304
#define PG_SMEM  (2 * PG_STAGE)

__device__ __forceinline__ void gemm_128x256_core(
    const f16* __restrict__ Ah, const f16* __restrict__ Bh,
    const float* __restrict__ bias, bool out_f32,
    float* __restrict__ Cf, f16* __restrict__ C1)
{
    extern __shared__ __align__(1024) char smdyn[];
    const uint32_t sbase = smem_u32(smdyn);
    const int tid = threadIdx.x;
    const int wid = tid >> 5, lane = tid & 31;
    const int wm = (wid & 1) * 64;
    const int wn = (wid >> 1) * 64;
    const int row0 = blockIdx.y * 128;
    const int n0 = blockIdx.x * 256;

    uint32_t abase[4];
    #pragma unroll
    for (int mi = 0; mi < 4; mi++) {
        int r = wm + mi * 16 + (lane & 15);
        int hi = lane >> 4;
        abase[mi] = r * 128 + ((hi ^ (r & 7)) << 4);
    }
    uint32_t bbase[4];
    #pragma unroll
    for (int p = 0; p < 4; p++) {
        int g2 = lane >> 3;
        int r = wn + p * 16 + ((g2 >> 1) << 3) + (lane & 7);
        bbase[p] = r * 128 + (((g2 & 1) ^ (r & 7)) << 4);
    }

    float acc[4][8][4];
    #pragma unroll
    for (int mi = 0; mi < 4; mi++)
        #pragma unroll
        for (int ni = 0; ni < 8; ni++)
            #pragma unroll
            for (int q = 0; q < 4; q++) acc[mi][ni][q] = 0.0f;

    #pragma unroll
    for (int i = 0; i < 2; i++) {
        uint32_t sb = sbase + i * PG_STAGE;
        int k0 = i * 128;
        load_rows64(sb + PG_A0, Ah, row0, k0,      E_DIM, 4);
        load_rows64(sb + PG_A1, Ah, row0, k0 + 64, E_DIM, 4);
        load_rows64(sb + PG_B0, Bh, n0,   k0,      E_DIM, 8);
        load_rows64(sb + PG_B1, Bh, n0,   k0 + 64, E_DIM, 8);
        CP_COMMIT();
    }

    const int NC = E_DIM / 128;   // 16
    for (int c = 0; c < NC; c++) {
        CP_WAIT1();
        __syncthreads();
        const uint32_t sb = sbase + (c & 1) * PG_STAGE;
        #pragma unroll
        for (int ks = 0; ks < 8; ks++) {
            const uint32_t asub = sb + ((ks & 4) ? PG_A1 : PG_A0);
            const uint32_t bsub = sb + ((ks & 4) ? PG_B1 : PG_B0);
            const uint32_t kx = (ks & 3) << 5;
            uint32_t ah[4][4], bh[8][2];
            #pragma unroll
            for (int mi = 0; mi < 4; mi++)
                ldsm4(ah[mi], asub + (abase[mi] ^ kx));
            #pragma unroll
            for (int p = 0; p < 4; p++) {
                uint32_t t4[4];
                ldsm4(t4, bsub + (bbase[p] ^ kx));
                bh[2 * p][0] = t4[0]; bh[2 * p][1] = t4[1];
                bh[2 * p + 1][0] = t4[2]; bh[2 * p + 1][1] = t4[3];
            }
            #pragma unroll
            for (int mi = 0; mi < 4; mi++)
                #pragma unroll
                for (int ni = 0; ni < 8; ni++)
                    mma_f16(acc[mi][ni], ah[mi], bh[ni]);
        }
        __syncthreads();
        if (c + 2 < NC) {
            uint32_t sb2 = sbase + (c & 1) * PG_STAGE;
            int k0 = (c + 2) * 128;
            load_rows64(sb2 + PG_A0, Ah, row0, k0,      E_DIM, 4);
            load_rows64(sb2 + PG_A1, Ah, row0, k0 + 64, E_DIM, 4);
            load_rows64(sb2 + PG_B0, Bh, n0,   k0,      E_DIM, 8);
            load_rows64(sb2 + PG_B1, Bh, n0,   k0 + 64, E_DIM, 8);
        }
        CP_COMMIT();
    }

    const int lg = lane >> 2;
    const int lc2 = (lane & 3) * 2;
    #pragma unroll
    for (int mi = 0; mi < 4; mi++) {
        #pragma unroll
        for (int half = 0; half < 2; half++) {
            int row = row0 + wm + mi * 16 + lg + half * 8;
            #pragma unroll
            for (int ni = 0; ni < 8; ni++) {
                int col = n0 + wn + ni * 8 + lc2;
                float v0 = acc[mi][ni][half * 2 + 0] + bias[col];
                float v1 = acc[mi][ni][half * 2 + 1] + bias[col + 1];
                if (out_f32) {
                    *reinterpret_cast<float2*>(Cf + (size_t)row * E_DIM + col) = make_float2(v0, v1);
                } else {
                    *reinterpret_cast<uint32_t*>(C1 + (size_t)row * E_DIM + col) =
                        (uint32_t)__half_as_ushort(__float2half_rn(v0)) |
                        ((uint32_t)__half_as_ushort(__float2half_rn(v1)) << 16);
                }
            }
        }
    }
}

// fused K/V projections: grid (8, 128, 2)
__global__ __launch_bounds__(256, 1) void k_kv(
    const f16* __restrict__ xh, const f16* __restrict__ whBase,
    const float* __restrict__ bk, const float* __restrict__ bv)
{
    const int z = blockIdx.z;
    const size_t WSZ = (size_t)E_DIM * E_DIM;
    const f16* Bh = whBase + (size_t)(z + 1) * WSZ;          // Wk, Wv
    const float* bias = (z == 0) ? bk : bv;
    f16* C1 = (z == 0) ? g_Kh : g_Vh;
    gemm_128x256_core(xh, Bh, bias, false, nullptr, C1);
}

// final output: OUT = x @ Mt[b]^T + fbias[b]   (grid (8, 128))
__global__ __launch_bounds__(256, 1) void k_out(float* __restrict__ out)
{
    const int b = blockIdx.y >> 5;
    gemm_128x256_core(g_xh, g_M + (size_t)b * E_DIM * E_DIM,
                      g_fbias + b * E_DIM, true, out, nullptr);
}

// ---------------- M build: Mt[b][n][j] = sum_k PB[b][n][k] * Wq[k][j] --------
// A = PB (normal), B = Wq trans-loaded ([k][j] memory, frag needs (j,k)).
// grid (8, 16, 4): n-block 128 rows, j-block 256 cols, batch.
__global__ __launch_bounds__(256, 1) void k_mbuild(const f16* __restrict__ wq)
{
    extern __shared__ __align__(1024) char smdyn[];
    const uint32_t sbase = smem_u32(smdyn);
    const int tid = threadIdx.x;
    const int wid = tid >> 5, lane = tid & 31;
    const int wm = (wid & 1) * 64;
    const int wn = (wid >> 1) * 64;
    const int b = blockIdx.z;
    const int row0 = blockIdx.y * 128;     // n
    const int j0 = blockIdx.x * 256;       // j
    const f16* Ah = g_PB + (size_t)b * E_DIM * E_DIM;
    f16* Mout = g_M + (size_t)b * E_DIM * E_DIM;
    const int q = lane >> 3;

    uint32_t abase[4];
    #pragma unroll
    for (int mi = 0; mi < 4; mi++) {
        int r = wm + mi * 16 + (lane & 15);
        int hi = lane >> 4;
        abase[mi] = r * 128 + ((hi ^ (r & 7)) << 4);
    }
    // B trans frags (kv_mma-validated pattern, 512B rows)
    uint32_t btbase[4];
    #pragma unroll
    for (int p = 0; p < 4; p++) {
        int r0 = ((q & 1) << 3) + (lane & 7);
        int cc = ((wn + p * 16) >> 3) + (q >> 1);
        btbase[p] = r0 * 512 + ((cc ^ (r0 & 7)) << 4);
    }

    float acc[4][8][4];
    #pragma unroll
    for (int mi = 0; mi < 4; mi++)
        #pragma unroll
        for (int ni = 0; ni < 8; ni++)
            #pragma unroll
            for (int qq = 0; qq < 4; qq++) acc[mi][ni][qq] = 0.0f;

    #pragma unroll
    for (int i = 0; i < 2; i++) {
        uint32_t sb = sbase + i * PG_STAGE;
        int k0 = i * 128;
        load_rows64(sb + PG_A0, Ah, row0, k0,      E_DIM, 4);
        load_rows64(sb + PG_A1, Ah, row0, k0 + 64, E_DIM, 4);
        load_trans_tile(sb + PG_B0, wq, k0,      j0, E_DIM);
        load_trans_tile(sb + PG_B1, wq, k0 + 64, j0, E_DIM);
        CP_COMMIT();
    }

    const int NC = E_DIM / 128;   // 16
    for (int c = 0; c < NC; c++) {
        CP_WAIT1();
        __syncthreads();
        const uint32_t sb = sbase + (c & 1) * PG_STAGE;
        #pragma unroll
        for (int ks = 0; ks < 8; ks++) {
            const uint32_t asub = sb + ((ks & 4) ? PG_A1 : PG_A0);
            const uint32_t bsub = sb + ((ks & 4) ? PG_B1 : PG_B0);
            const uint32_t kx = (ks & 3) << 5;
            const uint32_t kofs = (uint32_t)(ks & 3) * 8192;   // 16 k-rows * 512B
            uint32_t ah[4][4], bh[8][2];
            #pragma unroll
            for (int mi = 0; mi < 4; mi++)
                ldsm4(ah[mi], asub + (abase[mi] ^ kx));
            #pragma unroll
            for (int p = 0; p < 4; p++) {
                uint32_t t4[4];
                ldsm4t(t4, bsub + btbase[p] + kofs);
                bh[2 * p][0] = t4[0]; bh[2 * p][1] = t4[1];
                bh[2 * p + 1][0] = t4[2]; bh[2 * p + 1][1] = t4[3];
            }
            #pragma unroll
            for (int mi = 0; mi < 4; mi++)
                #pragma unroll
                for (int ni = 0; ni < 8; ni++)
                    mma_f16(acc[mi][ni], ah[mi], bh[ni]);
        }
        __syncthreads();
        if (c + 2 < NC) {
            uint32_t sb2 = sbase + (c & 1) * PG_STAGE;
            int k0 = (c + 2) * 128;
            load_rows64(sb2 + PG_A0, Ah, row0, k0,      E_DIM, 4);
            load_rows64(sb2 + PG_A1, Ah, row0, k0 + 64, E_DIM, 4);
            load_trans_tile(sb2 + PG_B0, wq, k0,      j0, E_DIM);
            load_trans_tile(sb2 + PG_B1, wq, k0 + 64, j0, E_DIM);
        }
        CP_COMMIT();
    }

    const int lg = lane >> 2;
    const int lc2 = (lane & 3) * 2;
    #pragma unroll
    for (int mi = 0; mi < 4; mi++) {
        #pragma unroll
        for (int half = 0; half < 2; half++) {
            int row = row0 + wm + mi * 16 + lg + half * 8;
            #pragma unroll
            for (int ni = 0; ni < 8; ni++) {
                int col = j0 + wn + ni * 8 + lc2;
                *reinterpret_cast<uint32_t*>(Mout + (size_t)row * E_DIM + col) =
                    (uint32_t)__half_as_ushort(__float2half_rn(acc[mi][ni][half * 2 + 0])) |
                    ((uint32_t)__half_as_ushort(__float2half_rn(acc[mi][ni][half * 2 + 1])) << 16);
            }
        }
    }
}

// fbias[b][n] = bo[n] + sum_k bq[k] * PB[b][n][k]  (one warp per (b,n))
__global__ __launch_bounds__(256) void k_fbias(const float* __restrict__ bq,
                                               const float* __restrict__ bo)
{
    int gw = (blockIdx.x * 256 + threadIdx.x) >> 5;
    int lane = threadIdx.x & 31;
    int b = gw >> 11;
    int n = gw & 2047;
    const f16* row = g_PB + ((size_t)b * E_DIM + n) * E_DIM;
    float s = 0.0f;
    for (int k = lane; k < E_DIM; k += 32)
        s += __half2float(row[k]) * bq[k];
    #pragma unroll
    for (int o = 16; o > 0; o >>= 1) s += __shfl_xor_sync(0xFFFFFFFFu, s, o);
    if (lane == 0) g_fbias[b * E_DIM + n] = s + bo[n];
}

// ---------------- KV gemm (unchanged from R10) -------------------------------
#define KV_A 0
#define KV_B 16384
#define KV_STAGE 32768
#define KV_SMEM  (2 * KV_STAGE)

__device__ __forceinline__ void load_kv_tile(uint32_t sdst, const f16* __restrict__ g,
                                             int btrow0, int colh)
{
    const int t = threadIdx.x;
    #pragma unroll
    for (int i = 0; i < 4; i++) {
        int idx = t + i * 256;
        int r = idx >> 4, cc = idx & 15;
        const f16* src = g + (size_t)(btrow0 + r) * E_DIM + colh + cc * 8;
        cp_async16(sdst + r * 256 + ((cc ^ (r & 7)) << 4), src);
    }
}

__global__ __launch_bounds__(256, 1) void k_kv_mma()
{
    const int split = blockIdx.x;
    const int bh = blockIdx.z;
    const int b = bh >> 4;
    const int h = bh & 15;
    const int colh = h * 128;
    const int bt_begin = b * T_DIM + split * (T_DIM / KVSPLIT);

    extern __shared__ __align__(1024) char smdyn[];
    const uint32_t sbase = smem_u32(smdyn);
    const int tid = threadIdx.x;
    const int wid = tid >> 5, lane = tid & 31;
    const int wm = (wid & 1) * 64;
    const int wn = (wid >> 1) * 32;
    const int q = lane >> 3;

    uint32_t abase[4];
    #pragma unroll
    for (int mi = 0; mi < 4; mi++) {
        int r0 = ((q & 2) << 2) + (lane & 7);
        int cc = ((wm + mi * 16) >> 3) + (q & 1);
        abase[mi] = r0 * 256 + ((cc ^ (r0 & 7)) << 4);
    }
    uint32_t bbase[2];
    #pragma unroll
    for (int p = 0; p < 2; p++) {
        int r0 = ((q & 1) << 3) + (lane & 7);
        int cc = ((wn + p * 16) >> 3) + (q >> 1);
        bbase[p] = r0 * 256 + ((cc ^ (r0 & 7)) << 4);
    }

    float acc[4][4][4];
    #pragma unroll
    for (int mi = 0; mi < 4; mi++)
        #pragma unroll
        for (int ni = 0; ni < 4; ni++)
            #pragma unroll
            for (int qq = 0; qq < 4; qq++) acc[mi][ni][qq] = 0.0f;

    #pragma unroll
    for (int i = 0; i < 2; i++) {
        uint32_t sb = sbase + i * KV_STAGE;
        load_kv_tile(sb + KV_A, g_Kh, bt_begin + i * 64, colh);
        load_kv_tile(sb + KV_B, g_Vh, bt_begin + i * 64, colh);
        CP_COMMIT();
    }

    const int NC = (T_DIM / KVSPLIT) / 64;
    for (int c = 0; c < NC; c++) {
        CP_WAIT1();
        __syncthreads();
        const uint32_t sb = sbase + (c & 1) * KV_STAGE;
        #pragma unroll
        for (int ks = 0; ks < 4; ks++) {
            const uint32_t kofs = ks * 4096;
            uint32_t ah[4][4], bh[4][2];
            #pragma unroll
            for (int mi = 0; mi < 4; mi++)
                ldsm4t(ah[mi], sb + KV_A + abase[mi] + kofs);
            #pragma unroll
            for (int p = 0; p < 2; p++) {
                uint32_t t4[4];
                ldsm4t(t4, sb + KV_B + bbase[p] + kofs);
                bh[2 * p][0] = t4[0]; bh[2 * p][1] = t4[1];
                bh[2 * p + 1][0] = t4[2]; bh[2 * p + 1][1] = t4[3];
            }
            #pragma unroll
            for (int mi = 0; mi < 4; mi++)
                #pragma unroll
                for (int ni = 0; ni < 4; ni++)
                    mma_f16(acc[mi][ni], ah[mi], bh[ni]);
        }
        __syncthreads();
        if (c + 2 < NC) {
            uint32_t sb2 = sbase + (c & 1) * KV_STAGE;
            load_kv_tile(sb2 + KV_A, g_Kh, bt_begin + (c + 2) * 64, colh);
            load_kv_tile(sb2 + KV_B, g_Vh, bt_begin + (c + 2) * 64, colh);
        }
        CP_COMMIT();
    }

    float* Cg = g_KVp + ((size_t)(split * 64 + bh) << 14);
    const int lg = lane >> 2;
    const int lc2 = (lane & 3) * 2;
    #pragma unroll
    for (int mi = 0; mi < 4; mi++)
        #pragma unroll
        for (int half = 0; half < 2; half++) {
            int row = wm + mi * 16 + lg + half * 8;
            #pragma unroll
            for (int ni = 0; ni < 4; ni++) {
                int col = wn + ni * 8 + lc2;
                *reinterpret_cast<float2*>(Cg + row * D_DIM + col) =
                    make_float2(acc[mi][ni][half * 2 + 0], acc[mi][ni][half * 2 + 1]);
            }
        }
}

__global__ __launch_bounds__(256) void k_kvreduce()
{
    const float alpha = 0.08838834764831845f;
    int idx = blockIdx.x * 256 + threadIdx.x;
    float sv = 0.0f;
    #pragma unroll
    for (int p = 0; p < KVSPLIT; p++) sv += g_KVp[((size_t)p << 20) + idx];
    g_KVth[idx] = __float2half_rn(alpha * sv);
}

// ---------------- PB build (unchanged from R10) ------------------------------
#define AT_STAGE 16384
#define AT_SMEM  (3 * AT_STAGE)

__device__ __forceinline__ void load_tile128(uint32_t sdst, const f16* __restrict__ g,
                                             int row0, int col0, int ld) {
    const int t = threadIdx.x;
    #pragma unroll
    for (int i = 0; i < 2; i++) {
        int idx = t + i * 256;
        int r = idx >> 2, c = idx & 3;
        const f16* src = g + (size_t)(row0 + r) * ld + col0 + c * 8;
        uint32_t off = r * 64 + ((c ^ ((r >> 1) & 3)) << 4);
        cp_async16(sdst + off, src);
    }
}

__global__ __launch_bounds__(256) void k_pb(const f16* __restrict__ wo)
{
    const int bh = blockIdx.z;
    const int b = bh >> 4;
    const int h = bh & 15;
    const int row0 = blockIdx.y * 128;
    const f16* Ah = wo;
    const f16* Bh = g_KVth + ((size_t)bh << 14);
    const int acol = h * 128;
    f16* PBb = g_PB + (size_t)b * E_DIM * E_DIM;

    extern __shared__ __align__(1024) char smdyn[];
    const uint32_t sbase = smem_u32(smdyn);
    const int tid = threadIdx.x;
    const int wid = tid >> 5, lane = tid & 31;
    const int wm = (wid & 1) * 64;
    const int wn = (wid >> 1) * 32;

    uint32_t aoff[4][2];
    #pragma unroll
    for (int mi = 0; mi < 4; mi++) {
        int r = wm + mi * 16 + (lane & 15);
        #pragma unroll
        for (int ks = 0; ks < 2; ks++) {
            int kc = ks * 2 + (lane >> 4);
            aoff[mi][ks] = r * 64 + ((kc ^ ((r >> 1) & 3)) << 4);
        }
    }
    uint32_t boff[2][2];
    #pragma unroll
    for (int p = 0; p < 2; p++) {
        int g2 = lane >> 3;
        int r = wn + p * 16 + ((g2 >> 1) << 3) + (lane & 7);
        #pragma unroll
        for (int ks = 0; ks < 2; ks++) {
            int kc = ks * 2 + (g2 & 1);
            boff[p][ks] = r * 64 + ((kc ^ ((r >> 1) & 3)) << 4);
        }
    }

    float acc[4][4][4];
    #pragma unroll
    for (int mi = 0; mi < 4; mi++)
        #pragma unroll
        for (int ni = 0; ni < 4; ni++)
            #pragma unroll
            for (int qq = 0; qq < 4; qq++) acc[mi][ni][qq] = 0.0f;

    #pragma unroll
    for (int i = 0; i < 2; i++) {
        uint32_t sb = sbase + i * AT_STAGE;
        int k0 = i * 32;
        load_tile128(sb + 0,    Ah, row0, acol + k0, E_DIM);
        load_tile128(sb + 8192, Bh, 0, k0, D_DIM);
        CP_COMMIT();
    }

    for (int c = 0; c < 4; c++) {
        if (c + 2 < 4) {
            uint32_t sb = sbase + ((c + 2) % 3) * AT_STAGE;
            int k0 = (c + 2) * 32;
            load_tile128(sb + 0,    Ah, row0, acol + k0, E_DIM);
            load_tile128(sb + 8192, Bh, 0, k0, D_DIM);
        }
        CP_COMMIT();
        CP_WAIT2();
        __syncthreads();

        const uint32_t sb = sbase + (c % 3) * AT_STAGE;
        #pragma unroll
        for (int ks = 0; ks < 2; ks++) {
            uint32_t ah[4][4], bh[4][2];
            #pragma unroll
            for (int mi = 0; mi < 4; mi++)
                ldsm4(ah[mi], sb + aoff[mi][ks]);
            #pragma unroll
            for (int p = 0; p < 2; p++) {
                uint32_t t4[4];
                ldsm4(t4, sb + 8192 + boff[p][ks]);
                bh[2 * p][0] = t4[0]; bh[2 * p][1] = t4[1];
                bh[2 * p + 1][0] = t4[2]; bh[2 * p + 1][1] = t4[3];
            }
            #pragma unroll
            for (int mi = 0; mi < 4; mi++)
                #pragma unroll
                for (int ni = 0; ni < 4; ni++)
                    mma_f16(acc[mi][ni], ah[mi], bh[ni]);
        }
        __syncthreads();
    }

    const int lg = lane >> 2;
    const int lc2 = (lane & 3) * 2;
    #pragma unroll
    for (int mi = 0; mi < 4; mi++) {
        #pragma unroll
        for (int half = 0; half < 2; half++) {
            int row = row0 + wm + mi * 16 + lg + half * 8;
            #pragma unroll
            for (int ni = 0; ni < 4; ni++) {
                int col = h * 128 + wn + ni * 8 + lc2;
                *reinterpret_cast<uint32_t*>(PBb + (size_t)row * E_DIM + col) =
                    (uint32_t)__half_as_ushort(__float2half_rn(acc[mi][ni][half * 2 + 0])) |
                    ((uint32_t)__half_as_ushort(__float2half_rn(acc[mi][ni][half * 2 + 1])) << 16);
            }
        }
    }
}

// fused fp32 -> fp16 conversion: x then 4 weight matrices
__global__ __launch_bounds__(256) void k_split_all(
    const float* __restrict__ x,
    const float* __restrict__ Wq, const float* __restrict__ Wk,
    const float* __restrict__ Wv, const float* __restrict__ Wo,
    f16* __restrict__ xh, f16* __restrict__ whBase)
{
    const size_t WSZ4 = (size_t)E_DIM * E_DIM / 4;
    const size_t NX4  = (size_t)BT_DIM * E_DIM / 4;
    size_t i4 = (size_t)blockIdx.x * 256 + threadIdx.x;
    const float* src;
    f16* dst;
    if (i4 < NX4) {
        src = x; dst = xh;
    } else {
        size_t r = i4 - NX4;
        int w = (int)(r / WSZ4);
        i4 = r - (size_t)w * WSZ4;
        src = (w == 0) ? Wq : (w == 1) ? Wk : (w == 2) ? Wv : Wo;
        dst = whBase + (size_t)w * E_DIM * E_DIM;
    }
    float4 v = *reinterpret_cast<const float4*>(src + i4 * 4);
    uint32_t hw0 = (uint32_t)__half_as_ushort(__float2half_rn(v.x)) |
                   ((uint32_t)__half_as_ushort(__float2half_rn(v.y)) << 16);
    uint32_t hw1 = (uint32_t)__half_as_ushort(__float2half_rn(v.z)) |
                   ((uint32_t)__half_as_ushort(__float2half_rn(v.w)) << 16);
    *reinterpret_cast<uint2*>(dst + i4 * 4) = make_uint2(hw0, hw1);
}

// ---------------- launch -----------------------------------------------------
extern "C" void kernel_launch(void* const* d_in, const int* in_sizes, int n_in,
                              void* d_out, int out_size)
{
    const float* x  = (const float*)d_in[0];
    const float* Wq = (const float*)d_in[1];
    const float* bq = (const float*)d_in[2];
    const float* Wk = (const float*)d_in[3];
    const float* bk = (const float*)d_in[4];
    const float* Wv = (const float*)d_in[5];
    const float* bv = (const float*)d_in[6];
    const float* Wo = (const float*)d_in[7];
    const float* bo = (const float*)d_in[8];
    float* out = (float*)d_out;

    f16 *xh, *wh;
    cudaGetSymbolAddress((void**)&xh, g_xh);
    cudaGetSymbolAddress((void**)&wh, g_Wh);

    cudaFuncSetAttribute(k_kv,     cudaFuncAttributeMaxDynamicSharedMemorySize, PG_SMEM);
    cudaFuncSetAttribute(k_out,    cudaFuncAttributeMaxDynamicSharedMemorySize, PG_SMEM);
    cudaFuncSetAttribute(k_mbuild, cudaFuncAttributeMaxDynamicSharedMemorySize, PG_SMEM);
    cudaFuncSetAttribute(k_kv_mma, cudaFuncAttributeMaxDynamicSharedMemorySize, KV_SMEM);
    cudaFuncSetAttribute(k_pb,     cudaFuncAttributeMaxDynamicSharedMemorySize, AT_SMEM);

    const size_t WSZ = (size_t)E_DIM * E_DIM;
    const size_t total4 = ((size_t)BT_DIM * E_DIM + 4 * WSZ) / 4;

    k_split_all<<<(int)(total4 / 256), 256>>>(x, Wq, Wk, Wv, Wo, xh, wh);

    k_kv<<<dim3(E_DIM / 256, BT_DIM / 128, 2), 256, PG_SMEM>>>(xh, wh, bk, bv);

    k_kv_mma<<<dim3(KVSPLIT, 1, 64), 256, KV_SMEM>>>();
    k_kvreduce<<<(64 * D_DIM * D_DIM) / 256, 256>>>();

    k_pb<<<dim3(1, E_DIM / 128, 64), 256, AT_SMEM>>>(wh + 3 * WSZ);

    k_mbuild<<<dim3(E_DIM / 256, E_DIM / 128, B_DIM), 256, PG_SMEM>>>(wh + 0 * WSZ);
    k_fbias<<<(B_DIM * E_DIM * 32) / 256, 256>>>(bq, bo);

    k_out<<<dim3(E_DIM / 256, BT_DIM / 128), 256, PG_SMEM>>>(out);
}